// round 12
// baseline (speedup 1.0000x reference)
#include <cuda_runtime.h>
#include <cstdint>

#define S_SPANS 4096
#define K_ANT   64
#define N_MENT  4096
#define G_DIM   512
#define H_DIM   150
#define NPAD    160
#define AB_ROWS 16

#define ADDP 153   // sAdd row stride (floats)
#define MPRD 36    // raw M/A row stride (floats): transform bank = 4*gidx+tig+8s, conflict-free
#define WSTR 168   // sW row stride (uint32): B-frag bank = 8*tig+gidx, conflict-free

// ---------------- scratch (device globals; no allocation) ----------------
__device__ float g_A[N_MENT * H_DIM];      // g_i @ W1[0:512]
__device__ float g_B[N_MENT * H_DIM];      // g_i @ W1[512:1024]
__device__ float g_Ed[10 * H_DIM];         // dist_embed @ W1[1536:1556] + b1
__device__ float g_Eg[7 * H_DIM];          // genre_embed @ W1[1556:1576]
__device__ float g_Es[3 * H_DIM];          // speaker_embed @ W1[1576:1596]
__device__ uint32_t g_Wp[G_DIM * NPAD];    // W1[1024:1536] padded->[512][160], tf32 bits

// ---------------- SMEM layout (bytes) ----------------
#define SZ_MA   18432                       // 128*36*4
#define SZ_W    21504                       // 32*168*4
#define SZ_P    16384                       // 1024 frag-quads * 16B
#define OFF_M0  0                           // 2 buffers raw M
#define OFF_A0  36864                       // 2 buffers raw A
#define OFF_W0  73728                       // 2 buffers W
#define OFF_P   116736                      // 2 buffers product frags
#define OFF_ADD 149504                      // 128*153*4 = 78336
#define OFF_W2  227840                      // 160*4
#define OFF_MS  228480                      // 128*4
#define OFF_MID 228992                      // 128*4
#define OFF_AID 229504                      // 128*4
#define SMEM_TOTAL 230016
// epilogue scratch aliased into sProd (dead after last MMA):
#define OFF_PT  OFF_P                       // 128*4*4
#define OFF_SC  (OFF_P + 2048)              // 128*4

__device__ __forceinline__ uint32_t f2tf32(float f) {
    uint32_t u;
    asm("cvt.rna.tf32.f32 %0, %1;" : "=r"(u) : "f"(f));
    return u;
}
__device__ __forceinline__ uint32_t smem_u32(const void* p) {
    uint32_t a;
    asm("{ .reg .u64 t; cvta.to.shared.u64 t, %1; cvt.u32.u64 %0, t; }" : "=r"(a) : "l"(p));
    return a;
}
__device__ __forceinline__ void cp16(uint32_t dst, const void* src) {
    asm volatile("cp.async.cg.shared.global [%0], [%1], 16;" :: "r"(dst), "l"(src) : "memory");
}
#define CP_COMMIT() asm volatile("cp.async.commit_group;" ::: "memory")
#define CP_WAIT0()  asm volatile("cp.async.wait_group 0;" ::: "memory")

__device__ __forceinline__ void mma_tf32(float* d, const uint32_t* a, const uint32_t* b) {
    asm volatile(
        "mma.sync.aligned.m16n8k8.row.col.f32.tf32.tf32.f32 "
        "{%0,%1,%2,%3}, {%4,%5,%6,%7}, {%8,%9}, {%0,%1,%2,%3};"
        : "+f"(d[0]), "+f"(d[1]), "+f"(d[2]), "+f"(d[3])
        : "r"(a[0]), "r"(a[1]), "r"(a[2]), "r"(a[3]), "r"(b[0]), "r"(b[1]));
}

// ---------------- tiny tables ----------------
__global__ void tables_kernel(const float* __restrict__ dist_embed,
                              const float* __restrict__ genre_embed,
                              const float* __restrict__ speaker_embed,
                              const float* __restrict__ W1,
                              const float* __restrict__ b1) {
    int idx = blockIdx.x * blockDim.x + threadIdx.x;
    if (idx < 10 * H_DIM) {
        int d = idx / H_DIM, j = idx % H_DIM;
        float acc = b1[j];
        #pragma unroll
        for (int t = 0; t < 20; t++)
            acc += dist_embed[d * 20 + t] * W1[(1536 + t) * H_DIM + j];
        g_Ed[idx] = acc;
    } else if (idx < 17 * H_DIM) {
        int r = idx - 10 * H_DIM;
        int d = r / H_DIM, j = r % H_DIM;
        float acc = 0.f;
        #pragma unroll
        for (int t = 0; t < 20; t++)
            acc += genre_embed[d * 20 + t] * W1[(1556 + t) * H_DIM + j];
        g_Eg[r] = acc;
    } else if (idx < 20 * H_DIM) {
        int r = idx - 17 * H_DIM;
        int d = r / H_DIM, j = r % H_DIM;
        float acc = 0.f;
        #pragma unroll
        for (int t = 0; t < 20; t++)
            acc += speaker_embed[d * 20 + t] * W1[(1576 + t) * H_DIM + j];
        g_Es[r] = acc;
    }
}

// ---------------- W pack: [512][150] -> [512][160] tf32 bits ----------------
__global__ void packw_kernel(const float* __restrict__ W1) {
    int idx = blockIdx.x * blockDim.x + threadIdx.x;
    if (idx < G_DIM * NPAD) {
        int k = idx / NPAD, n = idx % NPAD;
        float v = (n < H_DIM) ? W1[(1024 + k) * H_DIM + n] : 0.f;
        g_Wp[idx] = f2tf32(v);
    }
}

// ---------------- A/B precompute ----------------
__global__ __launch_bounds__(160) void ab_kernel(const float* __restrict__ g_i,
                                                 const float* __restrict__ W1) {
    __shared__ float sg[AB_ROWS][G_DIM];
    int n0 = blockIdx.x * AB_ROWS;
    for (int idx = threadIdx.x; idx < AB_ROWS * G_DIM; idx += blockDim.x) {
        int r = idx / G_DIM, k = idx % G_DIM;
        sg[r][k] = g_i[(n0 + r) * G_DIM + k];
    }
    __syncthreads();
    int j = threadIdx.x;
    if (j < H_DIM) {
        float accA[AB_ROWS], accB[AB_ROWS];
        #pragma unroll
        for (int r = 0; r < AB_ROWS; r++) { accA[r] = 0.f; accB[r] = 0.f; }
        for (int k = 0; k < G_DIM; k++) {
            float wa = W1[k * H_DIM + j];
            float wb = W1[(G_DIM + k) * H_DIM + j];
            #pragma unroll
            for (int r = 0; r < AB_ROWS; r++) {
                float gv = sg[r][k];
                accA[r] += gv * wa;
                accB[r] += gv * wb;
            }
        }
        #pragma unroll
        for (int r = 0; r < AB_ROWS; r++) {
            g_A[(n0 + r) * H_DIM + j] = accA[r];
            g_B[(n0 + r) * H_DIM + j] = accB[r];
        }
    }
}

// ---------------- main: pipelined (cp.async / transform / mma) tf32 kernel ----------------
// CTA = 128 pairs = 2 spans, 512 threads = 16 warps (4 m-groups x 4 n-groups).
// Warp owns 2 m-tiles x 5 n-tiles. 16 K-chunks of 32.
// Pipeline: cp.async chunk c+2 | transform chunk c+1 (raw->frag smem) | MMA chunk c.
__global__ __launch_bounds__(512, 1) void main_kernel(
    const float* __restrict__ g_i, const float* __restrict__ ms,
    const float* __restrict__ W2, const float* __restrict__ b2,
    const int* __restrict__ mention_ids, const int* __restrict__ antecedent_ids,
    const int* __restrict__ distances, const int* __restrict__ genres,
    const int* __restrict__ speakers, const int* __restrict__ ant_counts,
    float* __restrict__ out)
{
    extern __shared__ __align__(16) char smem[];
    const uint32_t sbase = smem_u32(smem);
    float*    sAdd = (float*)(smem + OFF_ADD);
    float*    sW2  = (float*)(smem + OFF_W2);
    float*    sMS  = (float*)(smem + OFF_MS);
    int*      sm_m = (int*)(smem + OFF_MID);
    int*      sm_a = (int*)(smem + OFF_AID);

    const int t    = threadIdx.x;
    const int w    = t >> 5;
    const int lane = t & 31;
    const int gidx = lane >> 2;
    const int tig  = lane & 3;
    const int mg   = w >> 2;      // 0..3, 32 rows each
    const int ng   = w & 3;       // 0..3, 40 cols each
    const int pbase = blockIdx.x * 128;

    if (t < 128) {
        sm_m[t] = mention_ids[pbase + t];
        sm_a[t] = antecedent_ids[pbase + t];
    }
    if (t < NPAD) sW2[t] = (t < H_DIM) ? W2[t] : 0.f;
    __syncthreads();

    // ---- per-thread cp.async slot pointers (fixed across chunks) ----
    const float* srcM[2];
    const float* srcA[2];
    uint32_t dMA[2];
    #pragma unroll
    for (int i = 0; i < 2; i++) {
        int idx = t + 512 * i;
        int p = idx >> 3, q = idx & 7;
        srcM[i] = g_i + (size_t)sm_m[p] * G_DIM + 4 * q;
        srcA[i] = g_i + (size_t)sm_a[p] * G_DIM + 4 * q;
        dMA[i]  = (uint32_t)(p * MPRD + 4 * q) * 4u;
    }
    const uint32_t* srcW[3];
    uint32_t dW[3];
    bool vW[3];
    #pragma unroll
    for (int i = 0; i < 3; i++) {
        int idx = t + 512 * i;
        vW[i] = idx < 1280;
        int cidx = vW[i] ? idx : 0;
        int kk = cidx / 40, c16 = cidx % 40;
        srcW[i] = g_Wp + kk * NPAD + 4 * c16;
        dW[i]   = (uint32_t)(kk * WSTR + 4 * c16) * 4u;
    }

    // transform geometry: warp handles frag-blocks (mt16, s) for slot0/slot1
    const int tr_s    = w & 3;
    const int tr_mt0  = w >> 2;         // slot 0: mt16 = 0..3
    const int tr_mt1  = (w >> 2) + 4;   // slot 1: mt16 = 4..7
    const int tr_k0   = 8 * tr_s + tig;

    // ---- prologue ----
    // load chunk 0
    #pragma unroll
    for (int i = 0; i < 2; i++) {
        cp16(sbase + OFF_M0 + dMA[i], srcM[i]);
        cp16(sbase + OFF_A0 + dMA[i], srcA[i]);
    }
    #pragma unroll
    for (int i = 0; i < 3; i++)
        if (vW[i]) cp16(sbase + OFF_W0 + dW[i], srcW[i]);
    CP_COMMIT();
    CP_WAIT0();
    __syncthreads();
    // transform chunk 0 -> sProd[0]
    {
        const float* pM = (const float*)(smem + OFF_M0);
        const float* pA = (const float*)(smem + OFF_A0);
        uint32_t* pP = (uint32_t*)(smem + OFF_P);
        #pragma unroll
        for (int sl = 0; sl < 2; sl++) {
            int mt16 = sl ? tr_mt1 : tr_mt0;
            int r0 = (mt16 * 16 + gidx) * MPRD + tr_k0;
            int r1 = r0 + 8 * MPRD;
            uint4 q;
            q.x = f2tf32(pM[r0]     * pA[r0]);
            q.y = f2tf32(pM[r1]     * pA[r1]);
            q.z = f2tf32(pM[r0 + 4] * pA[r0 + 4]);
            q.w = f2tf32(pM[r1 + 4] * pA[r1 + 4]);
            *(uint4*)(pP + ((mt16 * 4 + tr_s) * 32 + lane) * 4) = q;
        }
    }
    // load chunk 1
    #pragma unroll
    for (int i = 0; i < 2; i++) {
        cp16(sbase + OFF_M0 + SZ_MA + dMA[i], srcM[i] + 32);
        cp16(sbase + OFF_A0 + SZ_MA + dMA[i], srcA[i] + 32);
    }
    #pragma unroll
    for (int i = 0; i < 3; i++)
        if (vW[i]) cp16(sbase + OFF_W0 + SZ_W + dW[i], srcW[i] + 32 * NPAD);
    CP_COMMIT();

    float acc[2][5][4];
    #pragma unroll
    for (int mt = 0; mt < 2; mt++)
        #pragma unroll
        for (int j = 0; j < 5; j++)
            #pragma unroll
            for (int e = 0; e < 4; e++) acc[mt][j][e] = 0.f;

    for (int c = 0; c < 16; c++) {
        const int b  = c & 1;
        const int bn = b ^ 1;

        CP_WAIT0();          // chunk c+1 raw arrived
        __syncthreads();     // sProd[c] (written last iter / prologue) visible

        // ---- issue cp.async for chunk c+2 into raw[b] (its old contents transformed last iter) ----
        if (c + 2 < 16) {
            const int cc = c + 2;
            #pragma unroll
            for (int i = 0; i < 2; i++) {
                cp16(sbase + OFF_M0 + b * SZ_MA + dMA[i], srcM[i] + cc * 32);
                cp16(sbase + OFF_A0 + b * SZ_MA + dMA[i], srcA[i] + cc * 32);
            }
            #pragma unroll
            for (int i = 0; i < 3; i++)
                if (vW[i]) cp16(sbase + OFF_W0 + b * SZ_W + dW[i], srcW[i] + cc * 32 * NPAD);
        }
        CP_COMMIT();

        // ---- MMA: consume sProd[b] + W[b] for chunk c ----
        {
            const uint32_t* pP = (const uint32_t*)(smem + OFF_P + b * SZ_P);
            const uint32_t* pW = (const uint32_t*)(smem + OFF_W0 + b * SZ_W);
            #pragma unroll
            for (int s = 0; s < 4; s++) {
                uint32_t afr[2][4];
                #pragma unroll
                for (int mt = 0; mt < 2; mt++) {
                    int mt16 = 2 * mg + mt;
                    uint4 q = *(const uint4*)(pP + ((mt16 * 4 + s) * 32 + lane) * 4);
                    afr[mt][0] = q.x; afr[mt][1] = q.y; afr[mt][2] = q.z; afr[mt][3] = q.w;
                }
                uint32_t bfr[5][2];
                #pragma unroll
                for (int j = 0; j < 5; j++) {
                    int n = 8 * (5 * ng + j) + gidx;
                    bfr[j][0] = pW[(8 * s + tig) * WSTR + n];
                    bfr[j][1] = pW[(8 * s + tig + 4) * WSTR + n];
                }
                #pragma unroll
                for (int mt = 0; mt < 2; mt++)
                    #pragma unroll
                    for (int j = 0; j < 5; j++)
                        mma_tf32(acc[mt][j], afr[mt], bfr[j]);
            }
        }

        // ---- transform: raw[bn] (chunk c+1) -> sProd[bn] ----
        if (c + 1 < 16) {
            const float* pM = (const float*)(smem + OFF_M0 + bn * SZ_MA);
            const float* pA = (const float*)(smem + OFF_A0 + bn * SZ_MA);
            uint32_t* pP = (uint32_t*)(smem + OFF_P + bn * SZ_P);
            #pragma unroll
            for (int sl = 0; sl < 2; sl++) {
                int mt16 = sl ? tr_mt1 : tr_mt0;
                int r0 = (mt16 * 16 + gidx) * MPRD + tr_k0;
                int r1 = r0 + 8 * MPRD;
                uint4 q;
                q.x = f2tf32(pM[r0]     * pA[r0]);
                q.y = f2tf32(pM[r1]     * pA[r1]);
                q.z = f2tf32(pM[r0 + 4] * pA[r0 + 4]);
                q.w = f2tf32(pM[r1 + 4] * pA[r1 + 4]);
                *(uint4*)(pP + ((mt16 * 4 + tr_s) * 32 + lane) * 4) = q;
            }
        }

        // ---- Add-gather rows [8c, 8c+8) (LDG latency drains into next wait) ----
        #pragma unroll 1
        for (int idx = t; idx < 8 * NPAD; idx += 512) {
            int pr = idx / NPAD, j = idx % NPAD;
            int p = 8 * c + pr;
            float v = 0.f;
            if (j < H_DIM) {
                int gp = pbase + p;
                int m = sm_m[p], a = sm_a[p];
                int d = distances[gp];
                int bkt = (d >= 1) + (d >= 2) + (d >= 3) + (d >= 4) +
                          (d >= 8) + (d >= 16) + (d >= 32) + (d >= 64);
                v = g_A[m * H_DIM + j] + g_B[a * H_DIM + j] + g_Ed[bkt * H_DIM + j] +
                    g_Eg[genres[gp] * H_DIM + j] + g_Es[speakers[gp] * H_DIM + j];
            }
            if (j < ADDP) sAdd[p * ADDP + j] = v;
        }
        if (t < 8) {
            int p = 8 * c + t;
            sMS[p] = ms[sm_m[p]] + ms[sm_a[p]] + b2[0];
        }
    }
    __syncthreads();

    float* sPt = (float*)(smem + OFF_PT);
    float* sSc = (float*)(smem + OFF_SC);

    // ---- epilogue: + Add, ReLU, dot W2 ----
    {
        float rp[2][2];
        #pragma unroll
        for (int mt = 0; mt < 2; mt++) { rp[mt][0] = 0.f; rp[mt][1] = 0.f; }
        #pragma unroll
        for (int mt = 0; mt < 2; mt++) {
            int rowA = 32 * mg + 16 * mt + gidx;
            int rowB = rowA + 8;
            #pragma unroll
            for (int j = 0; j < 5; j++) {
                int col0 = 8 * (5 * ng + j) + 2 * tig;
                float w0 = sW2[col0], w1 = sW2[col0 + 1];
                float h;
                h = acc[mt][j][0] + ((col0     < ADDP) ? sAdd[rowA * ADDP + col0]     : 0.f);
                rp[mt][0] += fmaxf(h, 0.f) * w0;
                h = acc[mt][j][1] + ((col0 + 1 < ADDP) ? sAdd[rowA * ADDP + col0 + 1] : 0.f);
                rp[mt][0] += fmaxf(h, 0.f) * w1;
                h = acc[mt][j][2] + ((col0     < ADDP) ? sAdd[rowB * ADDP + col0]     : 0.f);
                rp[mt][1] += fmaxf(h, 0.f) * w0;
                h = acc[mt][j][3] + ((col0 + 1 < ADDP) ? sAdd[rowB * ADDP + col0 + 1] : 0.f);
                rp[mt][1] += fmaxf(h, 0.f) * w1;
            }
        }
        #pragma unroll
        for (int off = 1; off <= 2; off <<= 1)
            #pragma unroll
            for (int mt = 0; mt < 2; mt++) {
                rp[mt][0] += __shfl_xor_sync(0xffffffffu, rp[mt][0], off);
                rp[mt][1] += __shfl_xor_sync(0xffffffffu, rp[mt][1], off);
            }
        if (tig == 0) {
            #pragma unroll
            for (int mt = 0; mt < 2; mt++) {
                int rowA = 32 * mg + 16 * mt + gidx;
                sPt[rowA * 4 + ng]       = rp[mt][0];
                sPt[(rowA + 8) * 4 + ng] = rp[mt][1];
            }
        }
    }
    __syncthreads();
    if (t < 128)
        sSc[t] = sPt[t * 4 + 0] + sPt[t * 4 + 1] + sPt[t * 4 + 2] + sPt[t * 4 + 3] + sMS[t];
    __syncthreads();

    // ---- fused per-span softmax (2 spans per CTA) ----
    if (w < 2) {
        int s = blockIdx.x * 2 + w;
        int cnt = ant_counts[s];
        float v0 = sSc[w * 64 + lane], v1 = sSc[w * 64 + lane + 32];
        bool val0 = lane < cnt, val1 = (lane + 32) < cnt;
        float mx = 0.f;  // epsilon logit = 0
        if (val0) mx = fmaxf(mx, v0);
        if (val1) mx = fmaxf(mx, v1);
        #pragma unroll
        for (int off = 16; off >= 1; off >>= 1)
            mx = fmaxf(mx, __shfl_xor_sync(0xffffffffu, mx, off));
        float e0 = val0 ? expf(v0 - mx) : 0.f;
        float e1 = val1 ? expf(v1 - mx) : 0.f;
        float sum = e0 + e1;
        #pragma unroll
        for (int off = 16; off >= 1; off >>= 1)
            sum += __shfl_xor_sync(0xffffffffu, sum, off);
        float eps = expf(-mx);
        sum += eps;
        float inv = 1.0f / sum;
        float* orow = out + (size_t)s * (K_ANT + 1);
        orow[lane]      = val0 ? e0 * inv : 1000.0f;
        orow[lane + 32] = val1 ? e1 * inv : 1000.0f;
        if (lane == 0) orow[K_ANT] = eps * inv;
    }
}

extern "C" void kernel_launch(void* const* d_in, const int* in_sizes, int n_in,
                              void* d_out, int out_size) {
    const float* g_i            = (const float*)d_in[0];
    const float* mention_scores = (const float*)d_in[1];
    const float* dist_embed     = (const float*)d_in[2];
    const float* genre_embed    = (const float*)d_in[3];
    const float* speaker_embed  = (const float*)d_in[4];
    const float* W1             = (const float*)d_in[5];
    const float* b1             = (const float*)d_in[6];
    const float* W2             = (const float*)d_in[7];
    const float* b2             = (const float*)d_in[8];
    const int*   mention_ids    = (const int*)d_in[9];
    const int*   antecedent_ids = (const int*)d_in[10];
    const int*   distances      = (const int*)d_in[11];
    const int*   genres         = (const int*)d_in[12];
    const int*   speakers       = (const int*)d_in[13];
    const int*   ant_counts     = (const int*)d_in[14];
    float* out = (float*)d_out;

    cudaFuncSetAttribute(main_kernel, cudaFuncAttributeMaxDynamicSharedMemorySize, SMEM_TOTAL);

    tables_kernel<<<(20 * H_DIM + 255) / 256, 256>>>(dist_embed, genre_embed,
                                                     speaker_embed, W1, b1);
    packw_kernel<<<(G_DIM * NPAD + 255) / 256, 256>>>(W1);
    ab_kernel<<<N_MENT / AB_ROWS, 160>>>(g_i, W1);
    main_kernel<<<S_SPANS / 2, 512, SMEM_TOTAL>>>(g_i, mention_scores, W2, b2,
                                                  mention_ids, antecedent_ids, distances,
                                                  genres, speakers, ant_counts, out);
}

// round 13
// speedup vs baseline: 1.5953x; 1.5953x over previous
#include <cuda_runtime.h>
#include <cstdint>

#define S_SPANS 4096
#define K_ANT   64
#define N_MENT  4096
#define G_DIM   512
#define H_DIM   150
#define NPAD    160
#define AB_ROWS 16

#define ADDP 153   // sAdd row stride (floats)
#define MPRD 36    // sM/sA row stride (floats): A-frag bank = 4*gidx+tig, conflict-free
#define WSTR 168   // sW row stride (uint32): B-frag bank = 8*tig+gidx, conflict-free

// ---------------- scratch (device globals; no allocation) ----------------
__device__ float g_A[N_MENT * H_DIM];      // g_i @ W1[0:512]
__device__ float g_B[N_MENT * H_DIM];      // g_i @ W1[512:1024]
__device__ float g_Ed[10 * H_DIM];         // dist_embed @ W1[1536:1556] + b1
__device__ float g_Eg[7 * H_DIM];          // genre_embed @ W1[1556:1576]
__device__ float g_Es[3 * H_DIM];          // speaker_embed @ W1[1576:1596]
__device__ uint32_t g_Wp[G_DIM * NPAD];    // W1[1024:1536] padded->[512][160], tf32 bits

// ---------------- SMEM layout (bytes) ----------------
#define SZ_MA   18432                       // 128*36*4
#define SZ_W    21504                       // 32*168*4
#define OFF_M0  0                           // 2 buffers
#define OFF_A0  36864                       // 2 buffers
#define OFF_W0  73728                       // 2 buffers
#define OFF_ADD 116736                      // 128*153*4 = 78336
#define OFF_W2  195072                      // 160*4
#define OFF_MS  195712                      // 128*4
#define OFF_MID 196224                      // 128*4
#define OFF_AID 196736                      // 128*4
#define OFF_PT  197248                      // 128*4*4
#define OFF_SC  199296                      // 128*4
#define SMEM_TOTAL 199808

__device__ __forceinline__ uint32_t f2tf32(float f) {
    uint32_t u;
    asm("cvt.rna.tf32.f32 %0, %1;" : "=r"(u) : "f"(f));
    return u;
}
__device__ __forceinline__ uint32_t smem_u32(const void* p) {
    uint32_t a;
    asm("{ .reg .u64 t; cvta.to.shared.u64 t, %1; cvt.u32.u64 %0, t; }" : "=r"(a) : "l"(p));
    return a;
}
__device__ __forceinline__ void cp16(uint32_t dst, const void* src) {
    asm volatile("cp.async.cg.shared.global [%0], [%1], 16;" :: "r"(dst), "l"(src) : "memory");
}
#define CP_COMMIT() asm volatile("cp.async.commit_group;" ::: "memory")
#define CP_WAIT1()  asm volatile("cp.async.wait_group 1;" ::: "memory")

__device__ __forceinline__ void mma_tf32(float* d, const uint32_t* a, const uint32_t* b) {
    asm volatile(
        "mma.sync.aligned.m16n8k8.row.col.f32.tf32.tf32.f32 "
        "{%0,%1,%2,%3}, {%4,%5,%6,%7}, {%8,%9}, {%0,%1,%2,%3};"
        : "+f"(d[0]), "+f"(d[1]), "+f"(d[2]), "+f"(d[3])
        : "r"(a[0]), "r"(a[1]), "r"(a[2]), "r"(a[3]), "r"(b[0]), "r"(b[1]));
}

// ---------------- tiny tables ----------------
__global__ void tables_kernel(const float* __restrict__ dist_embed,
                              const float* __restrict__ genre_embed,
                              const float* __restrict__ speaker_embed,
                              const float* __restrict__ W1,
                              const float* __restrict__ b1) {
    int idx = blockIdx.x * blockDim.x + threadIdx.x;
    if (idx < 10 * H_DIM) {
        int d = idx / H_DIM, j = idx % H_DIM;
        float acc = b1[j];
        #pragma unroll
        for (int t = 0; t < 20; t++)
            acc += dist_embed[d * 20 + t] * W1[(1536 + t) * H_DIM + j];
        g_Ed[idx] = acc;
    } else if (idx < 17 * H_DIM) {
        int r = idx - 10 * H_DIM;
        int d = r / H_DIM, j = r % H_DIM;
        float acc = 0.f;
        #pragma unroll
        for (int t = 0; t < 20; t++)
            acc += genre_embed[d * 20 + t] * W1[(1556 + t) * H_DIM + j];
        g_Eg[r] = acc;
    } else if (idx < 20 * H_DIM) {
        int r = idx - 17 * H_DIM;
        int d = r / H_DIM, j = r % H_DIM;
        float acc = 0.f;
        #pragma unroll
        for (int t = 0; t < 20; t++)
            acc += speaker_embed[d * 20 + t] * W1[(1576 + t) * H_DIM + j];
        g_Es[r] = acc;
    }
}

// ---------------- W pack: [512][150] -> [512][160] tf32 bits ----------------
__global__ void packw_kernel(const float* __restrict__ W1) {
    int idx = blockIdx.x * blockDim.x + threadIdx.x;
    if (idx < G_DIM * NPAD) {
        int k = idx / NPAD, n = idx % NPAD;
        float v = (n < H_DIM) ? W1[(1024 + k) * H_DIM + n] : 0.f;
        g_Wp[idx] = f2tf32(v);
    }
}

// ---------------- A/B precompute ----------------
__global__ __launch_bounds__(160) void ab_kernel(const float* __restrict__ g_i,
                                                 const float* __restrict__ W1) {
    __shared__ float sg[AB_ROWS][G_DIM];
    int n0 = blockIdx.x * AB_ROWS;
    for (int idx = threadIdx.x; idx < AB_ROWS * G_DIM; idx += blockDim.x) {
        int r = idx / G_DIM, k = idx % G_DIM;
        sg[r][k] = g_i[(n0 + r) * G_DIM + k];
    }
    __syncthreads();
    int j = threadIdx.x;
    if (j < H_DIM) {
        float accA[AB_ROWS], accB[AB_ROWS];
        #pragma unroll
        for (int r = 0; r < AB_ROWS; r++) { accA[r] = 0.f; accB[r] = 0.f; }
        for (int k = 0; k < G_DIM; k++) {
            float wa = W1[k * H_DIM + j];
            float wb = W1[(G_DIM + k) * H_DIM + j];
            #pragma unroll
            for (int r = 0; r < AB_ROWS; r++) {
                float gv = sg[r][k];
                accA[r] += gv * wa;
                accB[r] += gv * wb;
            }
        }
        #pragma unroll
        for (int r = 0; r < AB_ROWS; r++) {
            g_A[(n0 + r) * H_DIM + j] = accA[r];
            g_B[(n0 + r) * H_DIM + j] = accB[r];
        }
    }
}

// ---------------- main: cp.async-pipelined mma.sync tf32 fused kernel ----------------
// CTA = 128 pairs = 2 spans, 512 threads = 16 warps (4 m-groups x 4 n-groups).
// Warp owns 2 m-tiles (16 rows) x 5 n-tiles (8 cols). K = 16 chunks of 32, 2-stage pipeline.
// Add-gather hoisted to one upfront MLP burst (overlaps prologue cp.async).
__global__ __launch_bounds__(512, 1) void main_kernel(
    const float* __restrict__ g_i, const float* __restrict__ ms,
    const float* __restrict__ W2, const float* __restrict__ b2,
    const int* __restrict__ mention_ids, const int* __restrict__ antecedent_ids,
    const int* __restrict__ distances, const int* __restrict__ genres,
    const int* __restrict__ speakers, const int* __restrict__ ant_counts,
    float* __restrict__ out)
{
    extern __shared__ __align__(16) char smem[];
    const uint32_t sbase = smem_u32(smem);
    float*    sAdd = (float*)(smem + OFF_ADD);
    float*    sW2  = (float*)(smem + OFF_W2);
    float*    sMS  = (float*)(smem + OFF_MS);
    int*      sm_m = (int*)(smem + OFF_MID);
    int*      sm_a = (int*)(smem + OFF_AID);
    float*    sPt  = (float*)(smem + OFF_PT);
    float*    sSc  = (float*)(smem + OFF_SC);

    const int t    = threadIdx.x;
    const int w    = t >> 5;
    const int lane = t & 31;
    const int gidx = lane >> 2;
    const int tig  = lane & 3;
    const int mg   = w >> 2;      // 0..3, 32 rows each
    const int ng   = w & 3;       // 0..3, 40 cols each
    const int pbase = blockIdx.x * 128;

    if (t < 128) {
        sm_m[t] = mention_ids[pbase + t];
        sm_a[t] = antecedent_ids[pbase + t];
    }
    if (t < NPAD) sW2[t] = (t < H_DIM) ? W2[t] : 0.f;
    __syncthreads();

    // ---- per-thread cp.async slot pointers (fixed across chunks) ----
    const float* srcM[2];
    const float* srcA[2];
    uint32_t dMA[2];
    #pragma unroll
    for (int i = 0; i < 2; i++) {
        int idx = t + 512 * i;
        int p = idx >> 3, q = idx & 7;
        srcM[i] = g_i + (size_t)sm_m[p] * G_DIM + 4 * q;
        srcA[i] = g_i + (size_t)sm_a[p] * G_DIM + 4 * q;
        dMA[i]  = (uint32_t)(p * MPRD + 4 * q) * 4u;
    }
    const uint32_t* srcW[3];
    uint32_t dW[3];
    bool vW[3];
    #pragma unroll
    for (int i = 0; i < 3; i++) {
        int idx = t + 512 * i;
        vW[i] = idx < 1280;
        int cidx = vW[i] ? idx : 0;
        int kk = cidx / 40, c16 = cidx % 40;
        srcW[i] = g_Wp + kk * NPAD + 4 * c16;
        dW[i]   = (uint32_t)(kk * WSTR + 4 * c16) * 4u;
    }

    // ---- prologue: prefetch chunks 0,1 ----
    #pragma unroll
    for (int b = 0; b < 2; b++) {
        #pragma unroll
        for (int i = 0; i < 2; i++) {
            cp16(sbase + OFF_M0 + b * SZ_MA + dMA[i], srcM[i] + b * 32);
            cp16(sbase + OFF_A0 + b * SZ_MA + dMA[i], srcA[i] + b * 32);
        }
        #pragma unroll
        for (int i = 0; i < 3; i++)
            if (vW[i]) cp16(sbase + OFF_W0 + b * SZ_W + dW[i], srcW[i] + b * 32 * NPAD);
        CP_COMMIT();
    }

    // ---- upfront Add-gather: all 128 rows, one large-MLP burst ----
    // (overlaps the in-flight prologue cp.async; consumed only at the epilogue)
    #pragma unroll 2
    for (int idx = t; idx < 128 * NPAD; idx += 512) {
        int pr = idx / NPAD, j = idx % NPAD;
        float v = 0.f;
        if (j < H_DIM) {
            int gp = pbase + pr;
            int m = sm_m[pr], a = sm_a[pr];
            int d = distances[gp];
            int bkt = (d >= 1) + (d >= 2) + (d >= 3) + (d >= 4) +
                      (d >= 8) + (d >= 16) + (d >= 32) + (d >= 64);
            v = g_A[m * H_DIM + j] + g_B[a * H_DIM + j] + g_Ed[bkt * H_DIM + j] +
                g_Eg[genres[gp] * H_DIM + j] + g_Es[speakers[gp] * H_DIM + j];
        }
        if (j < ADDP) sAdd[pr * ADDP + j] = v;
    }
    if (t < 128)
        sMS[t] = ms[sm_m[t]] + ms[sm_a[t]] + b2[0];

    float acc[2][5][4];
    #pragma unroll
    for (int mt = 0; mt < 2; mt++)
        #pragma unroll
        for (int j = 0; j < 5; j++)
            #pragma unroll
            for (int e = 0; e < 4; e++) acc[mt][j][e] = 0.f;

    for (int c = 0; c < 16; c++) {
        const int b = c & 1;
        const float*    pM = (const float*)(smem + OFF_M0 + b * SZ_MA);
        const float*    pA = (const float*)(smem + OFF_A0 + b * SZ_MA);
        const uint32_t* pW = (const uint32_t*)(smem + OFF_W0 + b * SZ_W);

        CP_WAIT1();
        __syncthreads();

        // ---- compute: 4 k-steps of m16n8k8, product formed in registers ----
        #pragma unroll
        for (int s = 0; s < 4; s++) {
            uint32_t afr[2][4];
            #pragma unroll
            for (int mt = 0; mt < 2; mt++) {
                int r0 = (32 * mg + 16 * mt + gidx) * MPRD + 8 * s + tig;
                int r1 = r0 + 8 * MPRD;
                afr[mt][0] = f2tf32(pM[r0]     * pA[r0]);
                afr[mt][1] = f2tf32(pM[r1]     * pA[r1]);
                afr[mt][2] = f2tf32(pM[r0 + 4] * pA[r0 + 4]);
                afr[mt][3] = f2tf32(pM[r1 + 4] * pA[r1 + 4]);
            }
            uint32_t bfr[5][2];
            #pragma unroll
            for (int j = 0; j < 5; j++) {
                int n = 8 * (5 * ng + j) + gidx;
                bfr[j][0] = pW[(8 * s + tig) * WSTR + n];
                bfr[j][1] = pW[(8 * s + tig + 4) * WSTR + n];
            }
            #pragma unroll
            for (int mt = 0; mt < 2; mt++)
                #pragma unroll
                for (int j = 0; j < 5; j++)
                    mma_tf32(acc[mt][j], afr[mt], bfr[j]);
        }

        __syncthreads();   // all reads of buffer b finished

        // ---- prefetch chunk c+2 into buffer b ----
        if (c + 2 < 16) {
            const int cc = c + 2;
            #pragma unroll
            for (int i = 0; i < 2; i++) {
                cp16(sbase + OFF_M0 + b * SZ_MA + dMA[i], srcM[i] + cc * 32);
                cp16(sbase + OFF_A0 + b * SZ_MA + dMA[i], srcA[i] + cc * 32);
            }
            #pragma unroll
            for (int i = 0; i < 3; i++)
                if (vW[i]) cp16(sbase + OFF_W0 + b * SZ_W + dW[i], srcW[i] + cc * 32 * NPAD);
        }
        CP_COMMIT();
    }
    __syncthreads();

    // ---- epilogue: + Add, ReLU, dot W2 ----
    {
        float rp[2][2];
        #pragma unroll
        for (int mt = 0; mt < 2; mt++) { rp[mt][0] = 0.f; rp[mt][1] = 0.f; }
        #pragma unroll
        for (int mt = 0; mt < 2; mt++) {
            int rowA = 32 * mg + 16 * mt + gidx;
            int rowB = rowA + 8;
            #pragma unroll
            for (int j = 0; j < 5; j++) {
                int col0 = 8 * (5 * ng + j) + 2 * tig;
                float w0 = sW2[col0], w1 = sW2[col0 + 1];
                float h;
                h = acc[mt][j][0] + ((col0     < ADDP) ? sAdd[rowA * ADDP + col0]     : 0.f);
                rp[mt][0] += fmaxf(h, 0.f) * w0;
                h = acc[mt][j][1] + ((col0 + 1 < ADDP) ? sAdd[rowA * ADDP + col0 + 1] : 0.f);
                rp[mt][0] += fmaxf(h, 0.f) * w1;
                h = acc[mt][j][2] + ((col0     < ADDP) ? sAdd[rowB * ADDP + col0]     : 0.f);
                rp[mt][1] += fmaxf(h, 0.f) * w0;
                h = acc[mt][j][3] + ((col0 + 1 < ADDP) ? sAdd[rowB * ADDP + col0 + 1] : 0.f);
                rp[mt][1] += fmaxf(h, 0.f) * w1;
            }
        }
        #pragma unroll
        for (int off = 1; off <= 2; off <<= 1)
            #pragma unroll
            for (int mt = 0; mt < 2; mt++) {
                rp[mt][0] += __shfl_xor_sync(0xffffffffu, rp[mt][0], off);
                rp[mt][1] += __shfl_xor_sync(0xffffffffu, rp[mt][1], off);
            }
        if (tig == 0) {
            #pragma unroll
            for (int mt = 0; mt < 2; mt++) {
                int rowA = 32 * mg + 16 * mt + gidx;
                sPt[rowA * 4 + ng]       = rp[mt][0];
                sPt[(rowA + 8) * 4 + ng] = rp[mt][1];
            }
        }
    }
    __syncthreads();
    if (t < 128)
        sSc[t] = sPt[t * 4 + 0] + sPt[t * 4 + 1] + sPt[t * 4 + 2] + sPt[t * 4 + 3] + sMS[t];
    __syncthreads();

    // ---- fused per-span softmax (2 spans per CTA) ----
    if (w < 2) {
        int s = blockIdx.x * 2 + w;
        int cnt = ant_counts[s];
        float v0 = sSc[w * 64 + lane], v1 = sSc[w * 64 + lane + 32];
        bool val0 = lane < cnt, val1 = (lane + 32) < cnt;
        float mx = 0.f;  // epsilon logit = 0
        if (val0) mx = fmaxf(mx, v0);
        if (val1) mx = fmaxf(mx, v1);
        #pragma unroll
        for (int off = 16; off >= 1; off >>= 1)
            mx = fmaxf(mx, __shfl_xor_sync(0xffffffffu, mx, off));
        float e0 = val0 ? expf(v0 - mx) : 0.f;
        float e1 = val1 ? expf(v1 - mx) : 0.f;
        float sum = e0 + e1;
        #pragma unroll
        for (int off = 16; off >= 1; off >>= 1)
            sum += __shfl_xor_sync(0xffffffffu, sum, off);
        float eps = expf(-mx);
        sum += eps;
        float inv = 1.0f / sum;
        float* orow = out + (size_t)s * (K_ANT + 1);
        orow[lane]      = val0 ? e0 * inv : 1000.0f;
        orow[lane + 32] = val1 ? e1 * inv : 1000.0f;
        if (lane == 0) orow[K_ANT] = eps * inv;
    }
}

extern "C" void kernel_launch(void* const* d_in, const int* in_sizes, int n_in,
                              void* d_out, int out_size) {
    const float* g_i            = (const float*)d_in[0];
    const float* mention_scores = (const float*)d_in[1];
    const float* dist_embed     = (const float*)d_in[2];
    const float* genre_embed    = (const float*)d_in[3];
    const float* speaker_embed  = (const float*)d_in[4];
    const float* W1             = (const float*)d_in[5];
    const float* b1             = (const float*)d_in[6];
    const float* W2             = (const float*)d_in[7];
    const float* b2             = (const float*)d_in[8];
    const int*   mention_ids    = (const int*)d_in[9];
    const int*   antecedent_ids = (const int*)d_in[10];
    const int*   distances      = (const int*)d_in[11];
    const int*   genres         = (const int*)d_in[12];
    const int*   speakers       = (const int*)d_in[13];
    const int*   ant_counts     = (const int*)d_in[14];
    float* out = (float*)d_out;

    cudaFuncSetAttribute(main_kernel, cudaFuncAttributeMaxDynamicSharedMemorySize, SMEM_TOTAL);

    tables_kernel<<<(20 * H_DIM + 255) / 256, 256>>>(dist_embed, genre_embed,
                                                     speaker_embed, W1, b1);
    packw_kernel<<<(G_DIM * NPAD + 255) / 256, 256>>>(W1);
    ab_kernel<<<N_MENT / AB_ROWS, 160>>>(g_i, W1);
    main_kernel<<<S_SPANS / 2, 512, SMEM_TOTAL>>>(g_i, mention_scores, W2, b2,
                                                  mention_ids, antecedent_ids, distances,
                                                  genres, speakers, ant_counts, out);
}

// round 14
// speedup vs baseline: 1.8981x; 1.1898x over previous
#include <cuda_runtime.h>
#include <cstdint>

#define S_SPANS 4096
#define K_ANT   64
#define N_MENT  4096
#define G_DIM   512
#define H_DIM   150
#define NPAD    160
#define AB_ROWS 16

#define ADDP 153   // sAdd row stride (floats)
#define MPRD 40    // raw M/A row stride (floats): LDS.64 phase bank-pair = (4g+t) mod 16, conflict-free
#define WROW 28    // packed-W per-lane row stride (uint32): LDS.128 quad = 7*lane mod 8, conflict-free

// per-chunk packed W: 4 ng * 32 lanes * 28 words
#define WCHUNK (4 * 32 * WROW)              // 3584 uint32 = 14336 B

// ---------------- scratch (device globals; no allocation) ----------------
__device__ float g_A[N_MENT * H_DIM];      // g_i @ W1[0:512]
__device__ float g_B[N_MENT * H_DIM];      // g_i @ W1[512:1024]
__device__ float g_Ed[10 * H_DIM];         // dist_embed @ W1[1536:1556] + b1
__device__ float g_Eg[7 * H_DIM];          // genre_embed @ W1[1556:1576]
__device__ float g_Es[3 * H_DIM];          // speaker_embed @ W1[1576:1596]
__device__ uint32_t g_Wb[16 * WCHUNK];     // W1c packed in bf16x2 fragment order per chunk

// ---------------- SMEM layout (bytes) ----------------
#define SZ_MA   20480                       // 128*40*4
#define SZ_W    14336                       // WCHUNK*4
#define OFF_M0  0                           // 2 buffers
#define OFF_A0  40960                       // 2 buffers
#define OFF_W0  81920                       // 2 buffers -> ends 110592
#define OFF_ADD 110592                      // 128*153*4 = 78336
#define OFF_W2  188928                      // 160*4
#define OFF_MS  189568                      // 128*4
#define OFF_MID 190080                      // 128*4
#define OFF_AID 190592                      // 128*4
#define OFF_PT  191104                      // 128*4*4
#define OFF_SC  193152                      // 128*4
#define SMEM_TOTAL 193664

__device__ __forceinline__ uint32_t smem_u32(const void* p) {
    uint32_t a;
    asm("{ .reg .u64 t; cvta.to.shared.u64 t, %1; cvt.u32.u64 %0, t; }" : "=r"(a) : "l"(p));
    return a;
}
__device__ __forceinline__ void cp16(uint32_t dst, const void* src) {
    asm volatile("cp.async.cg.shared.global [%0], [%1], 16;" :: "r"(dst), "l"(src) : "memory");
}
#define CP_COMMIT() asm volatile("cp.async.commit_group;" ::: "memory")
#define CP_WAIT1()  asm volatile("cp.async.wait_group 1;" ::: "memory")

// pack two f32 -> bf16x2: bits[31:16] = hi (k-odd), bits[15:0] = lo (k-even)
__device__ __forceinline__ uint32_t pack_bf16x2(float hi, float lo) {
    uint32_t d;
    asm("cvt.rn.bf16x2.f32 %0, %1, %2;" : "=r"(d) : "f"(hi), "f"(lo));
    return d;
}

__device__ __forceinline__ void mma_bf16(float* d, const uint32_t* a, const uint32_t* b) {
    asm volatile(
        "mma.sync.aligned.m16n8k16.row.col.f32.bf16.bf16.f32 "
        "{%0,%1,%2,%3}, {%4,%5,%6,%7}, {%8,%9}, {%0,%1,%2,%3};"
        : "+f"(d[0]), "+f"(d[1]), "+f"(d[2]), "+f"(d[3])
        : "r"(a[0]), "r"(a[1]), "r"(a[2]), "r"(a[3]), "r"(b[0]), "r"(b[1]));
}

// ---------------- tiny tables ----------------
__global__ void tables_kernel(const float* __restrict__ dist_embed,
                              const float* __restrict__ genre_embed,
                              const float* __restrict__ speaker_embed,
                              const float* __restrict__ W1,
                              const float* __restrict__ b1) {
    int idx = blockIdx.x * blockDim.x + threadIdx.x;
    if (idx < 10 * H_DIM) {
        int d = idx / H_DIM, j = idx % H_DIM;
        float acc = b1[j];
        #pragma unroll
        for (int t = 0; t < 20; t++)
            acc += dist_embed[d * 20 + t] * W1[(1536 + t) * H_DIM + j];
        g_Ed[idx] = acc;
    } else if (idx < 17 * H_DIM) {
        int r = idx - 10 * H_DIM;
        int d = r / H_DIM, j = r % H_DIM;
        float acc = 0.f;
        #pragma unroll
        for (int t = 0; t < 20; t++)
            acc += genre_embed[d * 20 + t] * W1[(1556 + t) * H_DIM + j];
        g_Eg[r] = acc;
    } else if (idx < 20 * H_DIM) {
        int r = idx - 17 * H_DIM;
        int d = r / H_DIM, j = r % H_DIM;
        float acc = 0.f;
        #pragma unroll
        for (int t = 0; t < 20; t++)
            acc += speaker_embed[d * 20 + t] * W1[(1576 + t) * H_DIM + j];
        g_Es[r] = acc;
    }
}

// ---------------- W pack: bf16x2 fragment-order layout ----------------
// Layout per chunk c: [ng][lane][o], o in [0,28): o<20 -> r=o&1, sj=o>>1, s=sj/5, j=sj%5.
// n = 40*ng + 8*j + (lane>>2); kbase = 32*c + 16*s + 2*(lane&3) + 8*r.
// word = bf16x2( lo = W1c[kbase][n], hi = W1c[kbase+1][n] ).
__global__ void packwb_kernel(const float* __restrict__ W1) {
    int idx = blockIdx.x * blockDim.x + threadIdx.x;
    if (idx >= 16 * WCHUNK) return;
    int c = idx / WCHUNK;
    int rem = idx % WCHUNK;
    int row = rem / WROW;
    int o = rem % WROW;
    uint32_t val = 0;
    if (o < 20) {
        int ng = row >> 5, lane = row & 31;
        int gidx = lane >> 2, tig = lane & 3;
        int r = o & 1, sj = o >> 1;
        int s = sj / 5, j = sj % 5;
        int n = 40 * ng + 8 * j + gidx;
        int kb = 32 * c + 16 * s + 2 * tig + 8 * r;
        float lo = (n < H_DIM) ? W1[(1024 + kb) * H_DIM + n] : 0.f;
        float hi = (n < H_DIM) ? W1[(1024 + kb + 1) * H_DIM + n] : 0.f;
        val = pack_bf16x2(hi, lo);
    }
    g_Wb[idx] = val;
}

// ---------------- A/B precompute ----------------
__global__ __launch_bounds__(160) void ab_kernel(const float* __restrict__ g_i,
                                                 const float* __restrict__ W1) {
    __shared__ float sg[AB_ROWS][G_DIM];
    int n0 = blockIdx.x * AB_ROWS;
    for (int idx = threadIdx.x; idx < AB_ROWS * G_DIM; idx += blockDim.x) {
        int r = idx / G_DIM, k = idx % G_DIM;
        sg[r][k] = g_i[(n0 + r) * G_DIM + k];
    }
    __syncthreads();
    int j = threadIdx.x;
    if (j < H_DIM) {
        float accA[AB_ROWS], accB[AB_ROWS];
        #pragma unroll
        for (int r = 0; r < AB_ROWS; r++) { accA[r] = 0.f; accB[r] = 0.f; }
        for (int k = 0; k < G_DIM; k++) {
            float wa = W1[k * H_DIM + j];
            float wb = W1[(G_DIM + k) * H_DIM + j];
            #pragma unroll
            for (int r = 0; r < AB_ROWS; r++) {
                float gv = sg[r][k];
                accA[r] += gv * wa;
                accB[r] += gv * wb;
            }
        }
        #pragma unroll
        for (int r = 0; r < AB_ROWS; r++) {
            g_A[(n0 + r) * H_DIM + j] = accA[r];
            g_B[(n0 + r) * H_DIM + j] = accB[r];
        }
    }
}

// ---------------- main: cp.async-pipelined bf16 m16n8k16 fused kernel ----------------
// CTA = 128 pairs = 2 spans, 512 threads = 16 warps (4 m-groups x 4 n-groups).
// Warp owns 2 m-tiles (16 rows) x 5 n-tiles (8 cols). K = 16 chunks of 32 (2 k16-steps each).
__global__ __launch_bounds__(512, 1) void main_kernel(
    const float* __restrict__ g_i, const float* __restrict__ ms,
    const float* __restrict__ W2, const float* __restrict__ b2,
    const int* __restrict__ mention_ids, const int* __restrict__ antecedent_ids,
    const int* __restrict__ distances, const int* __restrict__ genres,
    const int* __restrict__ speakers, const int* __restrict__ ant_counts,
    float* __restrict__ out)
{
    extern __shared__ __align__(16) char smem[];
    const uint32_t sbase = smem_u32(smem);
    float*    sAdd = (float*)(smem + OFF_ADD);
    float*    sW2  = (float*)(smem + OFF_W2);
    float*    sMS  = (float*)(smem + OFF_MS);
    int*      sm_m = (int*)(smem + OFF_MID);
    int*      sm_a = (int*)(smem + OFF_AID);
    float*    sPt  = (float*)(smem + OFF_PT);
    float*    sSc  = (float*)(smem + OFF_SC);

    const int t    = threadIdx.x;
    const int w    = t >> 5;
    const int lane = t & 31;
    const int gidx = lane >> 2;
    const int tig  = lane & 3;
    const int mg   = w >> 2;      // 0..3, 32 rows each
    const int ng   = w & 3;       // 0..3, 40 cols each
    const int pbase = blockIdx.x * 128;

    if (t < 128) {
        sm_m[t] = mention_ids[pbase + t];
        sm_a[t] = antecedent_ids[pbase + t];
    }
    if (t < NPAD) sW2[t] = (t < H_DIM) ? W2[t] : 0.f;
    __syncthreads();

    // ---- per-thread cp.async slot pointers (fixed across chunks) ----
    const float* srcM[2];
    const float* srcA[2];
    uint32_t dMA[2];
    #pragma unroll
    for (int i = 0; i < 2; i++) {
        int idx = t + 512 * i;
        int p = idx >> 3, q = idx & 7;
        srcM[i] = g_i + (size_t)sm_m[p] * G_DIM + 4 * q;
        srcA[i] = g_i + (size_t)sm_a[p] * G_DIM + 4 * q;
        dMA[i]  = (uint32_t)(p * MPRD + 4 * q) * 4u;
    }
    // W: per chunk 896 16B-granules; slot0 = t (all), slot1 = t+512 (if < 896)
    const bool vW1 = (t + 512) < (WCHUNK / 4);

    // ---- prologue: prefetch chunks 0,1 ----
    #pragma unroll
    for (int b = 0; b < 2; b++) {
        #pragma unroll
        for (int i = 0; i < 2; i++) {
            cp16(sbase + OFF_M0 + b * SZ_MA + dMA[i], srcM[i] + b * 32);
            cp16(sbase + OFF_A0 + b * SZ_MA + dMA[i], srcA[i] + b * 32);
        }
        cp16(sbase + OFF_W0 + b * SZ_W + t * 16, g_Wb + b * WCHUNK + t * 4);
        if (vW1) cp16(sbase + OFF_W0 + b * SZ_W + (t + 512) * 16, g_Wb + b * WCHUNK + (t + 512) * 4);
        CP_COMMIT();
    }

    // ---- upfront Add-gather: all 128 rows, one large-MLP burst ----
    #pragma unroll 2
    for (int idx = t; idx < 128 * NPAD; idx += 512) {
        int pr = idx / NPAD, j = idx % NPAD;
        float v = 0.f;
        if (j < H_DIM) {
            int gp = pbase + pr;
            int m = sm_m[pr], a = sm_a[pr];
            int d = distances[gp];
            int bkt = (d >= 1) + (d >= 2) + (d >= 3) + (d >= 4) +
                      (d >= 8) + (d >= 16) + (d >= 32) + (d >= 64);
            v = g_A[m * H_DIM + j] + g_B[a * H_DIM + j] + g_Ed[bkt * H_DIM + j] +
                g_Eg[genres[gp] * H_DIM + j] + g_Es[speakers[gp] * H_DIM + j];
        }
        if (j < ADDP) sAdd[pr * ADDP + j] = v;
    }
    if (t < 128)
        sMS[t] = ms[sm_m[t]] + ms[sm_a[t]] + b2[0];

    float acc[2][5][4];
    #pragma unroll
    for (int mt = 0; mt < 2; mt++)
        #pragma unroll
        for (int j = 0; j < 5; j++)
            #pragma unroll
            for (int e = 0; e < 4; e++) acc[mt][j][e] = 0.f;

    const uint32_t wrow = (uint32_t)((ng * 32 + lane) * WROW);

    for (int c = 0; c < 16; c++) {
        const int b = c & 1;
        const float*    pM = (const float*)(smem + OFF_M0 + b * SZ_MA);
        const float*    pA = (const float*)(smem + OFF_A0 + b * SZ_MA);
        const uint32_t* pW = (const uint32_t*)(smem + OFF_W0 + b * SZ_W);

        CP_WAIT1();
        __syncthreads();

        // ---- B fragments: 5 x LDS.128 (packed bf16x2, fragment order) ----
        uint32_t wb[20];
        #pragma unroll
        for (int i = 0; i < 5; i++) {
            uint4 q = *(const uint4*)(pW + wrow + 4 * i);
            wb[4 * i + 0] = q.x; wb[4 * i + 1] = q.y;
            wb[4 * i + 2] = q.z; wb[4 * i + 3] = q.w;
        }

        // ---- compute: 2 k16-steps of m16n8k16 ----
        #pragma unroll
        for (int s = 0; s < 2; s++) {
            uint32_t afr[2][4];
            #pragma unroll
            for (int mt = 0; mt < 2; mt++) {
                int base = (32 * mg + 16 * mt + gidx) * MPRD + 16 * s + 2 * tig;
                float2 mA = *(const float2*)(pM + base);
                float2 aA = *(const float2*)(pA + base);
                float2 mB = *(const float2*)(pM + base + 8 * MPRD);
                float2 aB = *(const float2*)(pA + base + 8 * MPRD);
                float2 mC = *(const float2*)(pM + base + 8);
                float2 aC = *(const float2*)(pA + base + 8);
                float2 mD = *(const float2*)(pM + base + 8 * MPRD + 8);
                float2 aD = *(const float2*)(pA + base + 8 * MPRD + 8);
                afr[mt][0] = pack_bf16x2(mA.y * aA.y, mA.x * aA.x);
                afr[mt][1] = pack_bf16x2(mB.y * aB.y, mB.x * aB.x);
                afr[mt][2] = pack_bf16x2(mC.y * aC.y, mC.x * aC.x);
                afr[mt][3] = pack_bf16x2(mD.y * aD.y, mD.x * aD.x);
            }
            #pragma unroll
            for (int mt = 0; mt < 2; mt++)
                #pragma unroll
                for (int j = 0; j < 5; j++) {
                    uint32_t bfr[2] = { wb[(s * 5 + j) * 2], wb[(s * 5 + j) * 2 + 1] };
                    mma_bf16(acc[mt][j], afr[mt], bfr);
                }
        }

        __syncthreads();   // all reads of buffer b finished

        // ---- prefetch chunk c+2 into buffer b ----
        if (c + 2 < 16) {
            const int cc = c + 2;
            #pragma unroll
            for (int i = 0; i < 2; i++) {
                cp16(sbase + OFF_M0 + b * SZ_MA + dMA[i], srcM[i] + cc * 32);
                cp16(sbase + OFF_A0 + b * SZ_MA + dMA[i], srcA[i] + cc * 32);
            }
            cp16(sbase + OFF_W0 + b * SZ_W + t * 16, g_Wb + cc * WCHUNK + t * 4);
            if (vW1) cp16(sbase + OFF_W0 + b * SZ_W + (t + 512) * 16, g_Wb + cc * WCHUNK + (t + 512) * 4);
        }
        CP_COMMIT();
    }
    __syncthreads();

    // ---- epilogue: + Add, ReLU, dot W2 ----
    {
        float rp[2][2];
        #pragma unroll
        for (int mt = 0; mt < 2; mt++) { rp[mt][0] = 0.f; rp[mt][1] = 0.f; }
        #pragma unroll
        for (int mt = 0; mt < 2; mt++) {
            int rowA = 32 * mg + 16 * mt + gidx;
            int rowB = rowA + 8;
            #pragma unroll
            for (int j = 0; j < 5; j++) {
                int col0 = 8 * (5 * ng + j) + 2 * tig;
                float w0 = sW2[col0], w1 = sW2[col0 + 1];
                float h;
                h = acc[mt][j][0] + ((col0     < ADDP) ? sAdd[rowA * ADDP + col0]     : 0.f);
                rp[mt][0] += fmaxf(h, 0.f) * w0;
                h = acc[mt][j][1] + ((col0 + 1 < ADDP) ? sAdd[rowA * ADDP + col0 + 1] : 0.f);
                rp[mt][0] += fmaxf(h, 0.f) * w1;
                h = acc[mt][j][2] + ((col0     < ADDP) ? sAdd[rowB * ADDP + col0]     : 0.f);
                rp[mt][1] += fmaxf(h, 0.f) * w0;
                h = acc[mt][j][3] + ((col0 + 1 < ADDP) ? sAdd[rowB * ADDP + col0 + 1] : 0.f);
                rp[mt][1] += fmaxf(h, 0.f) * w1;
            }
        }
        #pragma unroll
        for (int off = 1; off <= 2; off <<= 1)
            #pragma unroll
            for (int mt = 0; mt < 2; mt++) {
                rp[mt][0] += __shfl_xor_sync(0xffffffffu, rp[mt][0], off);
                rp[mt][1] += __shfl_xor_sync(0xffffffffu, rp[mt][1], off);
            }
        if (tig == 0) {
            #pragma unroll
            for (int mt = 0; mt < 2; mt++) {
                int rowA = 32 * mg + 16 * mt + gidx;
                sPt[rowA * 4 + ng]       = rp[mt][0];
                sPt[(rowA + 8) * 4 + ng] = rp[mt][1];
            }
        }
    }
    __syncthreads();
    if (t < 128)
        sSc[t] = sPt[t * 4 + 0] + sPt[t * 4 + 1] + sPt[t * 4 + 2] + sPt[t * 4 + 3] + sMS[t];
    __syncthreads();

    // ---- fused per-span softmax (2 spans per CTA) ----
    if (w < 2) {
        int s = blockIdx.x * 2 + w;
        int cnt = ant_counts[s];
        float v0 = sSc[w * 64 + lane], v1 = sSc[w * 64 + lane + 32];
        bool val0 = lane < cnt, val1 = (lane + 32) < cnt;
        float mx = 0.f;  // epsilon logit = 0
        if (val0) mx = fmaxf(mx, v0);
        if (val1) mx = fmaxf(mx, v1);
        #pragma unroll
        for (int off = 16; off >= 1; off >>= 1)
            mx = fmaxf(mx, __shfl_xor_sync(0xffffffffu, mx, off));
        float e0 = val0 ? expf(v0 - mx) : 0.f;
        float e1 = val1 ? expf(v1 - mx) : 0.f;
        float sum = e0 + e1;
        #pragma unroll
        for (int off = 16; off >= 1; off >>= 1)
            sum += __shfl_xor_sync(0xffffffffu, sum, off);
        float eps = expf(-mx);
        sum += eps;
        float inv = 1.0f / sum;
        float* orow = out + (size_t)s * (K_ANT + 1);
        orow[lane]      = val0 ? e0 * inv : 1000.0f;
        orow[lane + 32] = val1 ? e1 * inv : 1000.0f;
        if (lane == 0) orow[K_ANT] = eps * inv;
    }
}

extern "C" void kernel_launch(void* const* d_in, const int* in_sizes, int n_in,
                              void* d_out, int out_size) {
    const float* g_i            = (const float*)d_in[0];
    const float* mention_scores = (const float*)d_in[1];
    const float* dist_embed     = (const float*)d_in[2];
    const float* genre_embed    = (const float*)d_in[3];
    const float* speaker_embed  = (const float*)d_in[4];
    const float* W1             = (const float*)d_in[5];
    const float* b1             = (const float*)d_in[6];
    const float* W2             = (const float*)d_in[7];
    const float* b2             = (const float*)d_in[8];
    const int*   mention_ids    = (const int*)d_in[9];
    const int*   antecedent_ids = (const int*)d_in[10];
    const int*   distances      = (const int*)d_in[11];
    const int*   genres         = (const int*)d_in[12];
    const int*   speakers       = (const int*)d_in[13];
    const int*   ant_counts     = (const int*)d_in[14];
    float* out = (float*)d_out;

    cudaFuncSetAttribute(main_kernel, cudaFuncAttributeMaxDynamicSharedMemorySize, SMEM_TOTAL);

    tables_kernel<<<(20 * H_DIM + 255) / 256, 256>>>(dist_embed, genre_embed,
                                                     speaker_embed, W1, b1);
    packwb_kernel<<<(16 * WCHUNK + 255) / 256, 256>>>(W1);
    ab_kernel<<<N_MENT / AB_ROWS, 160>>>(g_i, W1);
    main_kernel<<<S_SPANS / 2, 512, SMEM_TOTAL>>>(g_i, mention_scores, W2, b2,
                                                  mention_ids, antecedent_ids, distances,
                                                  genres, speakers, ant_counts, out);
}

// round 15
// speedup vs baseline: 2.1037x; 1.1083x over previous
#include <cuda_runtime.h>
#include <cstdint>

#define S_SPANS 4096
#define K_ANT   64
#define N_MENT  4096
#define G_DIM   512
#define H_DIM   150
#define NPAD    160
#define AB_ROWS 16

#define ADDP 153   // sAdd row stride (floats)
#define MAW  20    // M/A tile row stride in 32-bit words (80B): bank=(20g+tig)%32 all-distinct
#define WROW 44    // packed-W per-(ng,lane) row stride (uint32): LDS.128 quad = 11*lane mod 8, conflict-free

// per-chunk packed W: 2 ng * 32 lanes * 44 words
#define WCHUNK (2 * 32 * WROW)              // 2816 uint32 = 11264 B

// ---------------- scratch (device globals; no allocation) ----------------
__device__ float g_A[N_MENT * H_DIM];      // g_i @ W1[0:512]
__device__ float g_B[N_MENT * H_DIM];      // g_i @ W1[512:1024]
__device__ float g_Ed[10 * H_DIM];         // dist_embed @ W1[1536:1556] + b1
__device__ float g_Eg[7 * H_DIM];          // genre_embed @ W1[1556:1576]
__device__ float g_Es[3 * H_DIM];          // speaker_embed @ W1[1576:1596]
__device__ uint32_t g_Wb[16 * WCHUNK];     // W1c packed bf16x2 fragment order per chunk
__device__ uint32_t g_gb[N_MENT * G_DIM / 2];  // g_i as bf16x2 (k-pairs packed)

// ---------------- SMEM layout (bytes) ----------------
#define SZ_MA   10240                       // 128*20*4
#define SZ_W    11264                       // WCHUNK*4
#define OFF_M0  0                           // 2 buffers -> 20480
#define OFF_A0  20480                       // 2 buffers -> 40960
#define OFF_W0  40960                       // 2 buffers -> 63488
#define OFF_ADD 63488                       // 128*153*4 = 78336 -> 141824
#define OFF_W2  141824                      // 160*4
#define OFF_MS  142464                      // 128*4
#define OFF_MID 142976                      // 128*4
#define OFF_AID 143488                      // 128*4
#define OFF_PT  144000                      // 128*2*4 = 1024
#define OFF_SC  145024                      // 128*4
#define SMEM_TOTAL 145536

__device__ __forceinline__ uint32_t smem_u32(const void* p) {
    uint32_t a;
    asm("{ .reg .u64 t; cvta.to.shared.u64 t, %1; cvt.u32.u64 %0, t; }" : "=r"(a) : "l"(p));
    return a;
}
__device__ __forceinline__ void cp16(uint32_t dst, const void* src) {
    asm volatile("cp.async.cg.shared.global [%0], [%1], 16;" :: "r"(dst), "l"(src) : "memory");
}
#define CP_COMMIT() asm volatile("cp.async.commit_group;" ::: "memory")
#define CP_WAIT1()  asm volatile("cp.async.wait_group 1;" ::: "memory")

// pack two f32 -> bf16x2: bits[31:16] = hi (k-odd), bits[15:0] = lo (k-even)
__device__ __forceinline__ uint32_t pack_bf16x2(float hi, float lo) {
    uint32_t d;
    asm("cvt.rn.bf16x2.f32 %0, %1, %2;" : "=r"(d) : "f"(hi), "f"(lo));
    return d;
}
__device__ __forceinline__ uint32_t hmul2(uint32_t a, uint32_t b) {
    uint32_t d;
    asm("mul.rn.bf16x2 %0, %1, %2;" : "=r"(d) : "r"(a), "r"(b));
    return d;
}

__device__ __forceinline__ void mma_bf16(float* d, const uint32_t* a, const uint32_t* b) {
    asm volatile(
        "mma.sync.aligned.m16n8k16.row.col.f32.bf16.bf16.f32 "
        "{%0,%1,%2,%3}, {%4,%5,%6,%7}, {%8,%9}, {%0,%1,%2,%3};"
        : "+f"(d[0]), "+f"(d[1]), "+f"(d[2]), "+f"(d[3])
        : "r"(a[0]), "r"(a[1]), "r"(a[2]), "r"(a[3]), "r"(b[0]), "r"(b[1]));
}

// ---------------- tiny tables ----------------
__global__ void tables_kernel(const float* __restrict__ dist_embed,
                              const float* __restrict__ genre_embed,
                              const float* __restrict__ speaker_embed,
                              const float* __restrict__ W1,
                              const float* __restrict__ b1) {
    int idx = blockIdx.x * blockDim.x + threadIdx.x;
    if (idx < 10 * H_DIM) {
        int d = idx / H_DIM, j = idx % H_DIM;
        float acc = b1[j];
        #pragma unroll
        for (int t = 0; t < 20; t++)
            acc += dist_embed[d * 20 + t] * W1[(1536 + t) * H_DIM + j];
        g_Ed[idx] = acc;
    } else if (idx < 17 * H_DIM) {
        int r = idx - 10 * H_DIM;
        int d = r / H_DIM, j = r % H_DIM;
        float acc = 0.f;
        #pragma unroll
        for (int t = 0; t < 20; t++)
            acc += genre_embed[d * 20 + t] * W1[(1556 + t) * H_DIM + j];
        g_Eg[r] = acc;
    } else if (idx < 20 * H_DIM) {
        int r = idx - 17 * H_DIM;
        int d = r / H_DIM, j = r % H_DIM;
        float acc = 0.f;
        #pragma unroll
        for (int t = 0; t < 20; t++)
            acc += speaker_embed[d * 20 + t] * W1[(1576 + t) * H_DIM + j];
        g_Es[r] = acc;
    }
}

// ---------------- g pack: f32 -> bf16x2 pairs ----------------
__global__ void packg_kernel(const float* __restrict__ g_i) {
    int idx = blockIdx.x * blockDim.x + threadIdx.x;
    if (idx < N_MENT * G_DIM / 2) {
        float lo = g_i[2 * idx], hi = g_i[2 * idx + 1];
        g_gb[idx] = pack_bf16x2(hi, lo);
    }
}

// ---------------- W pack: bf16x2 fragment-order layout ----------------
// Per chunk c: [ng(2)][lane(32)][o(44)], o<40: s=o/20, rem=o%20, j=rem>>1, r=rem&1.
// n = 80*ng + 8*j + (lane>>2); kb = 32*c + 16*s + 2*(lane&3) + 8*r.
// word = bf16x2( lo = W1c[kb][n], hi = W1c[kb+1][n] ).
__global__ void packwb_kernel(const float* __restrict__ W1) {
    int idx = blockIdx.x * blockDim.x + threadIdx.x;
    if (idx >= 16 * WCHUNK) return;
    int c = idx / WCHUNK;
    int rem0 = idx % WCHUNK;
    int row = rem0 / WROW;
    int o = rem0 % WROW;
    uint32_t val = 0;
    if (o < 40) {
        int ng = row >> 5, lane = row & 31;
        int gidx = lane >> 2, tig = lane & 3;
        int s = o / 20, rem = o % 20;
        int j = rem >> 1, r = rem & 1;
        int n = 80 * ng + 8 * j + gidx;
        int kb = 32 * c + 16 * s + 2 * tig + 8 * r;
        float lo = (n < H_DIM) ? W1[(1024 + kb) * H_DIM + n] : 0.f;
        float hi = (n < H_DIM) ? W1[(1024 + kb + 1) * H_DIM + n] : 0.f;
        val = pack_bf16x2(hi, lo);
    }
    g_Wb[idx] = val;
}

// ---------------- A/B precompute ----------------
__global__ __launch_bounds__(160) void ab_kernel(const float* __restrict__ g_i,
                                                 const float* __restrict__ W1) {
    __shared__ float sg[AB_ROWS][G_DIM];
    int n0 = blockIdx.x * AB_ROWS;
    for (int idx = threadIdx.x; idx < AB_ROWS * G_DIM; idx += blockDim.x) {
        int r = idx / G_DIM, k = idx % G_DIM;
        sg[r][k] = g_i[(n0 + r) * G_DIM + k];
    }
    __syncthreads();
    int j = threadIdx.x;
    if (j < H_DIM) {
        float accA[AB_ROWS], accB[AB_ROWS];
        #pragma unroll
        for (int r = 0; r < AB_ROWS; r++) { accA[r] = 0.f; accB[r] = 0.f; }
        for (int k = 0; k < G_DIM; k++) {
            float wa = W1[k * H_DIM + j];
            float wb = W1[(G_DIM + k) * H_DIM + j];
            #pragma unroll
            for (int r = 0; r < AB_ROWS; r++) {
                float gv = sg[r][k];
                accA[r] += gv * wa;
                accB[r] += gv * wb;
            }
        }
        #pragma unroll
        for (int r = 0; r < AB_ROWS; r++) {
            g_A[(n0 + r) * H_DIM + j] = accA[r];
            g_B[(n0 + r) * H_DIM + j] = accB[r];
        }
    }
}

// ---------------- main: cp.async-pipelined bf16 m16n8k16 fused kernel ----------------
// CTA = 128 pairs = 2 spans, 512 threads = 16 warps (8 m-groups x 2 n-groups).
// Warp owns 1 m-tile (16 rows) x 10 n-tiles (8 cols). K = 16 chunks of 32 (2 k16-steps).
__global__ __launch_bounds__(512, 1) void main_kernel(
    const float* __restrict__ ms,
    const float* __restrict__ W2, const float* __restrict__ b2,
    const int* __restrict__ mention_ids, const int* __restrict__ antecedent_ids,
    const int* __restrict__ distances, const int* __restrict__ genres,
    const int* __restrict__ speakers, const int* __restrict__ ant_counts,
    float* __restrict__ out)
{
    extern __shared__ __align__(16) char smem[];
    const uint32_t sbase = smem_u32(smem);
    float*    sAdd = (float*)(smem + OFF_ADD);
    float*    sW2  = (float*)(smem + OFF_W2);
    float*    sMS  = (float*)(smem + OFF_MS);
    int*      sm_m = (int*)(smem + OFF_MID);
    int*      sm_a = (int*)(smem + OFF_AID);
    float*    sPt  = (float*)(smem + OFF_PT);
    float*    sSc  = (float*)(smem + OFF_SC);

    const int t    = threadIdx.x;
    const int w    = t >> 5;
    const int lane = t & 31;
    const int gidx = lane >> 2;
    const int tig  = lane & 3;
    const int mg   = w >> 1;      // 0..7, 16 rows each
    const int ng   = w & 1;       // 0..1, 80 cols each
    const int pbase = blockIdx.x * 128;

    if (t < 128) {
        sm_m[t] = mention_ids[pbase + t];
        sm_a[t] = antecedent_ids[pbase + t];
    }
    if (t < NPAD) sW2[t] = (t < H_DIM) ? W2[t] : 0.f;
    __syncthreads();

    // ---- per-thread cp.async slot pointers (fixed across chunks) ----
    // M/A: 128 rows * 4 granules (16B=8 bf16) = 512 granules -> 1/thread
    const int p  = t >> 2;
    const int q  = t & 3;
    const uint32_t* srcM = g_gb + (size_t)sm_m[p] * (G_DIM / 2) + 4 * q;
    const uint32_t* srcA = g_gb + (size_t)sm_a[p] * (G_DIM / 2) + 4 * q;
    const uint32_t dMA = (uint32_t)(p * MAW + 4 * q) * 4u;
    // W: 704 granules per chunk: slot0 = t (t<512), slot1 = t+512 (t<192)
    const bool vW1 = (t + 512) < (WCHUNK / 4);

    // ---- prologue: prefetch chunks 0,1 ----
    #pragma unroll
    for (int b = 0; b < 2; b++) {
        cp16(sbase + OFF_M0 + b * SZ_MA + dMA, srcM + b * 16);
        cp16(sbase + OFF_A0 + b * SZ_MA + dMA, srcA + b * 16);
        cp16(sbase + OFF_W0 + b * SZ_W + t * 16, g_Wb + b * WCHUNK + t * 4);
        if (vW1) cp16(sbase + OFF_W0 + b * SZ_W + (t + 512) * 16, g_Wb + b * WCHUNK + (t + 512) * 4);
        CP_COMMIT();
    }

    // ---- upfront Add-gather: all 128 rows, one large-MLP burst ----
    #pragma unroll 2
    for (int idx = t; idx < 128 * NPAD; idx += 512) {
        int pr = idx / NPAD, j = idx % NPAD;
        float v = 0.f;
        if (j < H_DIM) {
            int gp = pbase + pr;
            int m = sm_m[pr], a = sm_a[pr];
            int d = distances[gp];
            int bkt = (d >= 1) + (d >= 2) + (d >= 3) + (d >= 4) +
                      (d >= 8) + (d >= 16) + (d >= 32) + (d >= 64);
            v = g_A[m * H_DIM + j] + g_B[a * H_DIM + j] + g_Ed[bkt * H_DIM + j] +
                g_Eg[genres[gp] * H_DIM + j] + g_Es[speakers[gp] * H_DIM + j];
        }
        if (j < ADDP) sAdd[pr * ADDP + j] = v;
    }
    if (t < 128)
        sMS[t] = ms[sm_m[t]] + ms[sm_a[t]] + b2[0];

    float acc[10][4];
    #pragma unroll
    for (int j = 0; j < 10; j++)
        #pragma unroll
        for (int e = 0; e < 4; e++) acc[j][e] = 0.f;

    const uint32_t wrow = (uint32_t)((ng * 32 + lane) * WROW);
    const int abase0 = (16 * mg + gidx) * MAW + tig;

    for (int c = 0; c < 16; c++) {
        const int b = c & 1;
        const uint32_t* pM = (const uint32_t*)(smem + OFF_M0 + b * SZ_MA);
        const uint32_t* pA = (const uint32_t*)(smem + OFF_A0 + b * SZ_MA);
        const uint32_t* pW = (const uint32_t*)(smem + OFF_W0 + b * SZ_W);

        CP_WAIT1();
        __syncthreads();

        // ---- compute: 2 k16-steps of m16n8k16 ----
        #pragma unroll
        for (int s = 0; s < 2; s++) {
            const int base = abase0 + 8 * s;
            uint32_t afr[4];
            afr[0] = hmul2(pM[base],             pA[base]);              // row g,   k 2tig..+1
            afr[1] = hmul2(pM[base + 8 * MAW],   pA[base + 8 * MAW]);    // row g+8
            afr[2] = hmul2(pM[base + 4],         pA[base + 4]);          // row g,   k +8
            afr[3] = hmul2(pM[base + 8 * MAW + 4], pA[base + 8 * MAW + 4]);
            uint32_t wb[20];
            #pragma unroll
            for (int i = 0; i < 5; i++) {
                uint4 qd = *(const uint4*)(pW + wrow + 20 * s + 4 * i);
                wb[4 * i + 0] = qd.x; wb[4 * i + 1] = qd.y;
                wb[4 * i + 2] = qd.z; wb[4 * i + 3] = qd.w;
            }
            #pragma unroll
            for (int j = 0; j < 10; j++) {
                uint32_t bfr[2] = { wb[2 * j], wb[2 * j + 1] };
                mma_bf16(acc[j], afr, bfr);
            }
        }

        __syncthreads();   // all reads of buffer b finished

        // ---- prefetch chunk c+2 into buffer b ----
        if (c + 2 < 16) {
            const int cc = c + 2;
            cp16(sbase + OFF_M0 + b * SZ_MA + dMA, srcM + cc * 16);
            cp16(sbase + OFF_A0 + b * SZ_MA + dMA, srcA + cc * 16);
            cp16(sbase + OFF_W0 + b * SZ_W + t * 16, g_Wb + cc * WCHUNK + t * 4);
            if (vW1) cp16(sbase + OFF_W0 + b * SZ_W + (t + 512) * 16, g_Wb + cc * WCHUNK + (t + 512) * 4);
        }
        CP_COMMIT();
    }
    __syncthreads();

    // ---- epilogue: + Add, ReLU, dot W2 ----
    {
        float rp0 = 0.f, rp1 = 0.f;
        const int rowA = 16 * mg + gidx;
        const int rowB = rowA + 8;
        #pragma unroll
        for (int j = 0; j < 10; j++) {
            int col0 = 8 * (10 * ng + j) + 2 * tig;
            float w0 = sW2[col0], w1 = sW2[col0 + 1];
            float h;
            h = acc[j][0] + ((col0     < ADDP) ? sAdd[rowA * ADDP + col0]     : 0.f);
            rp0 += fmaxf(h, 0.f) * w0;
            h = acc[j][1] + ((col0 + 1 < ADDP) ? sAdd[rowA * ADDP + col0 + 1] : 0.f);
            rp0 += fmaxf(h, 0.f) * w1;
            h = acc[j][2] + ((col0     < ADDP) ? sAdd[rowB * ADDP + col0]     : 0.f);
            rp1 += fmaxf(h, 0.f) * w0;
            h = acc[j][3] + ((col0 + 1 < ADDP) ? sAdd[rowB * ADDP + col0 + 1] : 0.f);
            rp1 += fmaxf(h, 0.f) * w1;
        }
        #pragma unroll
        for (int off = 1; off <= 2; off <<= 1) {
            rp0 += __shfl_xor_sync(0xffffffffu, rp0, off);
            rp1 += __shfl_xor_sync(0xffffffffu, rp1, off);
        }
        if (tig == 0) {
            sPt[rowA * 2 + ng] = rp0;
            sPt[rowB * 2 + ng] = rp1;
        }
    }
    __syncthreads();
    if (t < 128)
        sSc[t] = sPt[t * 2 + 0] + sPt[t * 2 + 1] + sMS[t];
    __syncthreads();

    // ---- fused per-span softmax (2 spans per CTA) ----
    if (w < 2) {
        int s = blockIdx.x * 2 + w;
        int cnt = ant_counts[s];
        float v0 = sSc[w * 64 + lane], v1 = sSc[w * 64 + lane + 32];
        bool val0 = lane < cnt, val1 = (lane + 32) < cnt;
        float mx = 0.f;  // epsilon logit = 0
        if (val0) mx = fmaxf(mx, v0);
        if (val1) mx = fmaxf(mx, v1);
        #pragma unroll
        for (int off = 16; off >= 1; off >>= 1)
            mx = fmaxf(mx, __shfl_xor_sync(0xffffffffu, mx, off));
        float e0 = val0 ? expf(v0 - mx) : 0.f;
        float e1 = val1 ? expf(v1 - mx) : 0.f;
        float sum = e0 + e1;
        #pragma unroll
        for (int off = 16; off >= 1; off >>= 1)
            sum += __shfl_xor_sync(0xffffffffu, sum, off);
        float eps = expf(-mx);
        sum += eps;
        float inv = 1.0f / sum;
        float* orow = out + (size_t)s * (K_ANT + 1);
        orow[lane]      = val0 ? e0 * inv : 1000.0f;
        orow[lane + 32] = val1 ? e1 * inv : 1000.0f;
        if (lane == 0) orow[K_ANT] = eps * inv;
    }
}

extern "C" void kernel_launch(void* const* d_in, const int* in_sizes, int n_in,
                              void* d_out, int out_size) {
    const float* g_i            = (const float*)d_in[0];
    const float* mention_scores = (const float*)d_in[1];
    const float* dist_embed     = (const float*)d_in[2];
    const float* genre_embed    = (const float*)d_in[3];
    const float* speaker_embed  = (const float*)d_in[4];
    const float* W1             = (const float*)d_in[5];
    const float* b1             = (const float*)d_in[6];
    const float* W2             = (const float*)d_in[7];
    const float* b2             = (const float*)d_in[8];
    const int*   mention_ids    = (const int*)d_in[9];
    const int*   antecedent_ids = (const int*)d_in[10];
    const int*   distances      = (const int*)d_in[11];
    const int*   genres         = (const int*)d_in[12];
    const int*   speakers       = (const int*)d_in[13];
    const int*   ant_counts     = (const int*)d_in[14];
    float* out = (float*)d_out;

    cudaFuncSetAttribute(main_kernel, cudaFuncAttributeMaxDynamicSharedMemorySize, SMEM_TOTAL);

    tables_kernel<<<(20 * H_DIM + 255) / 256, 256>>>(dist_embed, genre_embed,
                                                     speaker_embed, W1, b1);
    packg_kernel<<<(N_MENT * G_DIM / 2 + 255) / 256, 256>>>(g_i);
    packwb_kernel<<<(16 * WCHUNK + 255) / 256, 256>>>(W1);
    ab_kernel<<<N_MENT / AB_ROWS, 160>>>(g_i, W1);
    main_kernel<<<S_SPANS / 2, 512, SMEM_TOTAL>>>(mention_scores, W2, b2,
                                                  mention_ids, antecedent_ids, distances,
                                                  genres, speakers, ant_counts, out);
}

// round 16
// speedup vs baseline: 2.1744x; 1.0336x over previous
#include <cuda_runtime.h>
#include <cstdint>

#define S_SPANS 4096
#define K_ANT   64
#define N_MENT  4096
#define G_DIM   512
#define H_DIM   150
#define NPAD    160
#define ABR     8

#define ADDP 153   // sAdd row stride (floats)
#define MAW  20    // M/A tile row stride in 32-bit words (80B): bank=(20g+tig)%32 all-distinct
#define WROW 44    // packed-W per-(ng,lane) row stride (uint32): LDS.128 quad = 11*lane mod 8, conflict-free

// per-chunk packed W: 2 ng * 32 lanes * 44 words
#define WCHUNK (2 * 32 * WROW)              // 2816 uint32 = 11264 B

// prep_kernel index ranges
#define NPACKG (N_MENT * G_DIM / 2)         // 1048576
#define NPACKW (16 * WCHUNK)                // 45056
#define NTAB   (20 * H_DIM)                 // 3000
#define NPREP  (NPACKG + NPACKW + NTAB)

// ---------------- scratch (device globals; no allocation) ----------------
__device__ float g_A[N_MENT * H_DIM];      // g_i @ W1[0:512]
__device__ float g_B[N_MENT * H_DIM];      // g_i @ W1[512:1024]
__device__ float g_Ed[10 * H_DIM];         // dist_embed @ W1[1536:1556] + b1
__device__ float g_Eg[7 * H_DIM];          // genre_embed @ W1[1556:1576]
__device__ float g_Es[3 * H_DIM];          // speaker_embed @ W1[1576:1596]
__device__ uint32_t g_Wb[16 * WCHUNK];     // W1c packed bf16x2 fragment order per chunk
__device__ uint32_t g_gb[N_MENT * G_DIM / 2];  // g_i as bf16x2 (k-pairs packed)

// ---------------- SMEM layout (bytes) ----------------
#define SZ_MA   10240                       // 128*20*4
#define SZ_W    11264                       // WCHUNK*4
#define OFF_M0  0                           // 2 buffers -> 20480
#define OFF_A0  20480                       // 2 buffers -> 40960
#define OFF_W0  40960                       // 2 buffers -> 63488
#define OFF_ADD 63488                       // 128*153*4 = 78336 -> 141824
#define OFF_W2  141824                      // 160*4
#define OFF_MS  142464                      // 128*4
#define OFF_MID 142976                      // 128*4
#define OFF_AID 143488                      // 128*4
#define OFF_PT  144000                      // 128*2*4 = 1024
#define OFF_SC  145024                      // 128*4
#define SMEM_TOTAL 145536

__device__ __forceinline__ uint32_t smem_u32(const void* p) {
    uint32_t a;
    asm("{ .reg .u64 t; cvta.to.shared.u64 t, %1; cvt.u32.u64 %0, t; }" : "=r"(a) : "l"(p));
    return a;
}
__device__ __forceinline__ void cp16(uint32_t dst, const void* src) {
    asm volatile("cp.async.cg.shared.global [%0], [%1], 16;" :: "r"(dst), "l"(src) : "memory");
}
#define CP_COMMIT() asm volatile("cp.async.commit_group;" ::: "memory")
#define CP_WAIT1()  asm volatile("cp.async.wait_group 1;" ::: "memory")

// pack two f32 -> bf16x2: bits[31:16] = hi (k-odd), bits[15:0] = lo (k-even)
__device__ __forceinline__ uint32_t pack_bf16x2(float hi, float lo) {
    uint32_t d;
    asm("cvt.rn.bf16x2.f32 %0, %1, %2;" : "=r"(d) : "f"(hi), "f"(lo));
    return d;
}
__device__ __forceinline__ uint32_t hmul2(uint32_t a, uint32_t b) {
    uint32_t d;
    asm("mul.rn.bf16x2 %0, %1, %2;" : "=r"(d) : "r"(a), "r"(b));
    return d;
}

__device__ __forceinline__ void mma_bf16(float* d, const uint32_t* a, const uint32_t* b) {
    asm volatile(
        "mma.sync.aligned.m16n8k16.row.col.f32.bf16.bf16.f32 "
        "{%0,%1,%2,%3}, {%4,%5,%6,%7}, {%8,%9}, {%0,%1,%2,%3};"
        : "+f"(d[0]), "+f"(d[1]), "+f"(d[2]), "+f"(d[3])
        : "r"(a[0]), "r"(a[1]), "r"(a[2]), "r"(a[3]), "r"(b[0]), "r"(b[1]));
}

// ---------------- prep: fused packg + packwb + tables ----------------
__global__ void prep_kernel(const float* __restrict__ g_i,
                            const float* __restrict__ W1,
                            const float* __restrict__ b1,
                            const float* __restrict__ dist_embed,
                            const float* __restrict__ genre_embed,
                            const float* __restrict__ speaker_embed) {
    int idx = blockIdx.x * blockDim.x + threadIdx.x;
    if (idx < NPACKG) {
        // ---- packg: f32 -> bf16x2 pairs ----
        float lo = g_i[2 * idx], hi = g_i[2 * idx + 1];
        g_gb[idx] = pack_bf16x2(hi, lo);
        return;
    }
    idx -= NPACKG;
    if (idx < NPACKW) {
        // ---- packwb: W1c bf16x2 fragment-order layout ----
        int c = idx / WCHUNK;
        int rem0 = idx % WCHUNK;
        int row = rem0 / WROW;
        int o = rem0 % WROW;
        uint32_t val = 0;
        if (o < 40) {
            int ng = row >> 5, lane = row & 31;
            int gidx = lane >> 2, tig = lane & 3;
            int s = o / 20, rem = o % 20;
            int j = rem >> 1, r = rem & 1;
            int n = 80 * ng + 8 * j + gidx;
            int kb = 32 * c + 16 * s + 2 * tig + 8 * r;
            float lo = (n < H_DIM) ? W1[(1024 + kb) * H_DIM + n] : 0.f;
            float hi = (n < H_DIM) ? W1[(1024 + kb + 1) * H_DIM + n] : 0.f;
            val = pack_bf16x2(hi, lo);
        }
        g_Wb[idx] = val;
        return;
    }
    idx -= NPACKW;
    if (idx < 10 * H_DIM) {
        int d = idx / H_DIM, j = idx % H_DIM;
        float acc = b1[j];
        #pragma unroll
        for (int t = 0; t < 20; t++)
            acc += dist_embed[d * 20 + t] * W1[(1536 + t) * H_DIM + j];
        g_Ed[idx] = acc;
    } else if (idx < 17 * H_DIM) {
        int r = idx - 10 * H_DIM;
        int d = r / H_DIM, j = r % H_DIM;
        float acc = 0.f;
        #pragma unroll
        for (int t = 0; t < 20; t++)
            acc += genre_embed[d * 20 + t] * W1[(1556 + t) * H_DIM + j];
        g_Eg[r] = acc;
    } else if (idx < 20 * H_DIM) {
        int r = idx - 17 * H_DIM;
        int d = r / H_DIM, j = r % H_DIM;
        float acc = 0.f;
        #pragma unroll
        for (int t = 0; t < 20; t++)
            acc += speaker_embed[d * 20 + t] * W1[(1576 + t) * H_DIM + j];
        g_Es[r] = acc;
    }
}

// ---------------- A/B precompute: 1024 blocks (A/B split, 8 rows each) ----------------
__global__ __launch_bounds__(160) void ab_kernel(const float* __restrict__ g_i,
                                                 const float* __restrict__ W1) {
    __shared__ float sg[ABR][G_DIM];
    const int blk  = blockIdx.x;
    const int half = blk & 1;              // 0 -> A, 1 -> B
    const int n0   = (blk >> 1) * ABR;
    for (int idx = threadIdx.x; idx < ABR * G_DIM; idx += blockDim.x) {
        int r = idx / G_DIM, k = idx % G_DIM;
        sg[r][k] = g_i[(n0 + r) * G_DIM + k];
    }
    __syncthreads();
    int j = threadIdx.x;
    if (j < H_DIM) {
        float acc[ABR];
        #pragma unroll
        for (int r = 0; r < ABR; r++) acc[r] = 0.f;
        const float* Wp = W1 + (size_t)half * G_DIM * H_DIM + j;
        #pragma unroll 4
        for (int k = 0; k < G_DIM; k++) {
            float wv = Wp[(size_t)k * H_DIM];
            #pragma unroll
            for (int r = 0; r < ABR; r++) acc[r] += sg[r][k] * wv;
        }
        float* dst = half ? g_B : g_A;
        #pragma unroll
        for (int r = 0; r < ABR; r++) dst[(n0 + r) * H_DIM + j] = acc[r];
    }
}

// ---------------- main: cp.async-pipelined bf16 m16n8k16 fused kernel ----------------
// CTA = 128 pairs = 2 spans, 512 threads = 16 warps (8 m-groups x 2 n-groups).
// Warp owns 1 m-tile (16 rows) x 10 n-tiles (8 cols). K = 16 chunks of 32 (2 k16-steps).
__global__ __launch_bounds__(512, 1) void main_kernel(
    const float* __restrict__ ms,
    const float* __restrict__ W2, const float* __restrict__ b2,
    const int* __restrict__ mention_ids, const int* __restrict__ antecedent_ids,
    const int* __restrict__ distances, const int* __restrict__ genres,
    const int* __restrict__ speakers, const int* __restrict__ ant_counts,
    float* __restrict__ out)
{
    extern __shared__ __align__(16) char smem[];
    const uint32_t sbase = smem_u32(smem);
    float*    sAdd = (float*)(smem + OFF_ADD);
    float*    sW2  = (float*)(smem + OFF_W2);
    float*    sMS  = (float*)(smem + OFF_MS);
    int*      sm_m = (int*)(smem + OFF_MID);
    int*      sm_a = (int*)(smem + OFF_AID);
    float*    sPt  = (float*)(smem + OFF_PT);
    float*    sSc  = (float*)(smem + OFF_SC);

    const int t    = threadIdx.x;
    const int w    = t >> 5;
    const int lane = t & 31;
    const int gidx = lane >> 2;
    const int tig  = lane & 3;
    const int mg   = w >> 1;      // 0..7, 16 rows each
    const int ng   = w & 1;       // 0..1, 80 cols each
    const int pbase = blockIdx.x * 128;

    if (t < 128) {
        sm_m[t] = mention_ids[pbase + t];
        sm_a[t] = antecedent_ids[pbase + t];
    }
    if (t < NPAD) sW2[t] = (t < H_DIM) ? W2[t] : 0.f;
    __syncthreads();

    // ---- per-thread cp.async slot pointers (fixed across chunks) ----
    const int p  = t >> 2;
    const int q  = t & 3;
    const uint32_t* srcM = g_gb + (size_t)sm_m[p] * (G_DIM / 2) + 4 * q;
    const uint32_t* srcA = g_gb + (size_t)sm_a[p] * (G_DIM / 2) + 4 * q;
    const uint32_t dMA = (uint32_t)(p * MAW + 4 * q) * 4u;
    const bool vW1 = (t + 512) < (WCHUNK / 4);

    // ---- prologue: prefetch chunks 0,1 ----
    #pragma unroll
    for (int b = 0; b < 2; b++) {
        cp16(sbase + OFF_M0 + b * SZ_MA + dMA, srcM + b * 16);
        cp16(sbase + OFF_A0 + b * SZ_MA + dMA, srcA + b * 16);
        cp16(sbase + OFF_W0 + b * SZ_W + t * 16, g_Wb + b * WCHUNK + t * 4);
        if (vW1) cp16(sbase + OFF_W0 + b * SZ_W + (t + 512) * 16, g_Wb + b * WCHUNK + (t + 512) * 4);
        CP_COMMIT();
    }

    // ---- upfront Add-gather: all 128 rows, one large-MLP burst ----
    #pragma unroll 2
    for (int idx = t; idx < 128 * NPAD; idx += 512) {
        int pr = idx / NPAD, j = idx % NPAD;
        float v = 0.f;
        if (j < H_DIM) {
            int gp = pbase + pr;
            int m = sm_m[pr], a = sm_a[pr];
            int d = distances[gp];
            int bkt = (d >= 1) + (d >= 2) + (d >= 3) + (d >= 4) +
                      (d >= 8) + (d >= 16) + (d >= 32) + (d >= 64);
            v = g_A[m * H_DIM + j] + g_B[a * H_DIM + j] + g_Ed[bkt * H_DIM + j] +
                g_Eg[genres[gp] * H_DIM + j] + g_Es[speakers[gp] * H_DIM + j];
        }
        if (j < ADDP) sAdd[pr * ADDP + j] = v;
    }
    if (t < 128)
        sMS[t] = ms[sm_m[t]] + ms[sm_a[t]] + b2[0];

    float acc[10][4];
    #pragma unroll
    for (int j = 0; j < 10; j++)
        #pragma unroll
        for (int e = 0; e < 4; e++) acc[j][e] = 0.f;

    const uint32_t wrow = (uint32_t)((ng * 32 + lane) * WROW);
    const int abase0 = (16 * mg + gidx) * MAW + tig;

    for (int c = 0; c < 16; c++) {
        const int b = c & 1;
        const uint32_t* pM = (const uint32_t*)(smem + OFF_M0 + b * SZ_MA);
        const uint32_t* pA = (const uint32_t*)(smem + OFF_A0 + b * SZ_MA);
        const uint32_t* pW = (const uint32_t*)(smem + OFF_W0 + b * SZ_W);

        CP_WAIT1();
        __syncthreads();

        // ---- compute: 2 k16-steps of m16n8k16 ----
        #pragma unroll
        for (int s = 0; s < 2; s++) {
            const int base = abase0 + 8 * s;
            uint32_t afr[4];
            afr[0] = hmul2(pM[base],               pA[base]);
            afr[1] = hmul2(pM[base + 8 * MAW],     pA[base + 8 * MAW]);
            afr[2] = hmul2(pM[base + 4],           pA[base + 4]);
            afr[3] = hmul2(pM[base + 8 * MAW + 4], pA[base + 8 * MAW + 4]);
            uint32_t wb[20];
            #pragma unroll
            for (int i = 0; i < 5; i++) {
                uint4 qd = *(const uint4*)(pW + wrow + 20 * s + 4 * i);
                wb[4 * i + 0] = qd.x; wb[4 * i + 1] = qd.y;
                wb[4 * i + 2] = qd.z; wb[4 * i + 3] = qd.w;
            }
            #pragma unroll
            for (int j = 0; j < 10; j++) {
                uint32_t bfr[2] = { wb[2 * j], wb[2 * j + 1] };
                mma_bf16(acc[j], afr, bfr);
            }
        }

        __syncthreads();   // all reads of buffer b finished

        // ---- prefetch chunk c+2 into buffer b ----
        if (c + 2 < 16) {
            const int cc = c + 2;
            cp16(sbase + OFF_M0 + b * SZ_MA + dMA, srcM + cc * 16);
            cp16(sbase + OFF_A0 + b * SZ_MA + dMA, srcA + cc * 16);
            cp16(sbase + OFF_W0 + b * SZ_W + t * 16, g_Wb + cc * WCHUNK + t * 4);
            if (vW1) cp16(sbase + OFF_W0 + b * SZ_W + (t + 512) * 16, g_Wb + cc * WCHUNK + (t + 512) * 4);
        }
        CP_COMMIT();
    }
    __syncthreads();

    // ---- epilogue: + Add, ReLU, dot W2 ----
    {
        float rp0 = 0.f, rp1 = 0.f;
        const int rowA = 16 * mg + gidx;
        const int rowB = rowA + 8;
        #pragma unroll
        for (int j = 0; j < 10; j++) {
            int col0 = 8 * (10 * ng + j) + 2 * tig;
            float w0 = sW2[col0], w1 = sW2[col0 + 1];
            float h;
            h = acc[j][0] + ((col0     < ADDP) ? sAdd[rowA * ADDP + col0]     : 0.f);
            rp0 += fmaxf(h, 0.f) * w0;
            h = acc[j][1] + ((col0 + 1 < ADDP) ? sAdd[rowA * ADDP + col0 + 1] : 0.f);
            rp0 += fmaxf(h, 0.f) * w1;
            h = acc[j][2] + ((col0     < ADDP) ? sAdd[rowB * ADDP + col0]     : 0.f);
            rp1 += fmaxf(h, 0.f) * w0;
            h = acc[j][3] + ((col0 + 1 < ADDP) ? sAdd[rowB * ADDP + col0 + 1] : 0.f);
            rp1 += fmaxf(h, 0.f) * w1;
        }
        #pragma unroll
        for (int off = 1; off <= 2; off <<= 1) {
            rp0 += __shfl_xor_sync(0xffffffffu, rp0, off);
            rp1 += __shfl_xor_sync(0xffffffffu, rp1, off);
        }
        if (tig == 0) {
            sPt[rowA * 2 + ng] = rp0;
            sPt[rowB * 2 + ng] = rp1;
        }
    }
    __syncthreads();
    if (t < 128)
        sSc[t] = sPt[t * 2 + 0] + sPt[t * 2 + 1] + sMS[t];
    __syncthreads();

    // ---- fused per-span softmax (2 spans per CTA) ----
    if (w < 2) {
        int s = blockIdx.x * 2 + w;
        int cnt = ant_counts[s];
        float v0 = sSc[w * 64 + lane], v1 = sSc[w * 64 + lane + 32];
        bool val0 = lane < cnt, val1 = (lane + 32) < cnt;
        float mx = 0.f;  // epsilon logit = 0
        if (val0) mx = fmaxf(mx, v0);
        if (val1) mx = fmaxf(mx, v1);
        #pragma unroll
        for (int off = 16; off >= 1; off >>= 1)
            mx = fmaxf(mx, __shfl_xor_sync(0xffffffffu, mx, off));
        float e0 = val0 ? expf(v0 - mx) : 0.f;
        float e1 = val1 ? expf(v1 - mx) : 0.f;
        float sum = e0 + e1;
        #pragma unroll
        for (int off = 16; off >= 1; off >>= 1)
            sum += __shfl_xor_sync(0xffffffffu, sum, off);
        float eps = expf(-mx);
        sum += eps;
        float inv = 1.0f / sum;
        float* orow = out + (size_t)s * (K_ANT + 1);
        orow[lane]      = val0 ? e0 * inv : 1000.0f;
        orow[lane + 32] = val1 ? e1 * inv : 1000.0f;
        if (lane == 0) orow[K_ANT] = eps * inv;
    }
}

extern "C" void kernel_launch(void* const* d_in, const int* in_sizes, int n_in,
                              void* d_out, int out_size) {
    const float* g_i            = (const float*)d_in[0];
    const float* mention_scores = (const float*)d_in[1];
    const float* dist_embed     = (const float*)d_in[2];
    const float* genre_embed    = (const float*)d_in[3];
    const float* speaker_embed  = (const float*)d_in[4];
    const float* W1             = (const float*)d_in[5];
    const float* b1             = (const float*)d_in[6];
    const float* W2             = (const float*)d_in[7];
    const float* b2             = (const float*)d_in[8];
    const int*   mention_ids    = (const int*)d_in[9];
    const int*   antecedent_ids = (const int*)d_in[10];
    const int*   distances      = (const int*)d_in[11];
    const int*   genres         = (const int*)d_in[12];
    const int*   speakers       = (const int*)d_in[13];
    const int*   ant_counts     = (const int*)d_in[14];
    float* out = (float*)d_out;

    cudaFuncSetAttribute(main_kernel, cudaFuncAttributeMaxDynamicSharedMemorySize, SMEM_TOTAL);

    prep_kernel<<<(NPREP + 255) / 256, 256>>>(g_i, W1, b1, dist_embed,
                                              genre_embed, speaker_embed);
    ab_kernel<<<(N_MENT / ABR) * 2, 160>>>(g_i, W1);
    main_kernel<<<S_SPANS / 2, 512, SMEM_TOTAL>>>(mention_scores, W2, b2,
                                                  mention_ids, antecedent_ids, distances,
                                                  genres, speakers, ant_counts, out);
}

// round 17
// speedup vs baseline: 3.0650x; 1.4096x over previous
#include <cuda_runtime.h>
#include <cstdint>

#define S_SPANS 4096
#define K_ANT   64
#define N_MENT  4096
#define G_DIM   512
#define H_DIM   150
#define NPAD    160
#define ABR     8

#define ADDP 153   // sAdd row stride (floats)
#define MAW  20    // M/A tile row stride in 32-bit words (80B): bank=(20g+tig)%32 all-distinct
#define WROW 44    // packed-W per-(ng,lane) row stride (uint32): LDS.128 quad = 11*lane mod 8, conflict-free
#define ASTR 152   // padded row stride for g_A/g_B/Ed/Eg/Es (floats, 16B-aligned)
#define A4S  38    // ASTR in float4 units

// per-chunk packed W: 2 ng * 32 lanes * 44 words
#define WCHUNK (2 * 32 * WROW)              // 2816 uint32 = 11264 B

// prep_kernel index ranges
#define NPACKG (N_MENT * G_DIM / 2)         // 1048576
#define NPACKW (16 * WCHUNK)                // 45056
#define NTAB   (20 * H_DIM)                 // 3000
#define NPREP  (NPACKG + NPACKW + NTAB)

// ---------------- scratch (device globals; no allocation) ----------------
__device__ float g_A[N_MENT * ASTR];       // g_i @ W1[0:512], padded rows
__device__ float g_B[N_MENT * ASTR];       // g_i @ W1[512:1024]
__device__ float g_Ed[10 * ASTR];          // dist_embed @ W1[1536:1556] + b1
__device__ float g_Eg[7 * ASTR];           // genre_embed @ W1[1556:1576]
__device__ float g_Es[3 * ASTR];           // speaker_embed @ W1[1576:1596]
__device__ uint32_t g_Wb[16 * WCHUNK];     // W1c packed bf16x2 fragment order per chunk
__device__ uint32_t g_gb[N_MENT * G_DIM / 2];  // g_i as bf16x2 (k-pairs packed)

// ---------------- SMEM layout (bytes) ----------------
#define SZ_MA   10240                       // 128*20*4
#define SZ_W    11264                       // WCHUNK*4
#define OFF_M0  0                           // 3 buffers -> 30720
#define OFF_A0  30720                       // 3 buffers -> 61440
#define OFF_W0  61440                       // 3 buffers -> 95232
#define OFF_ADD 95232                       // 128*153*4 = 78336 -> 173568
#define OFF_W2  173568                      // 160*4
#define OFF_MS  174208                      // 128*4
#define OFF_MID 174720                      // 128*4
#define OFF_AID 175232                      // 128*4
#define OFF_PT  175744                      // 128*2*4 = 1024
#define OFF_SC  176768                      // 128*4
#define OFF_OM  177280                      // 128*4
#define OFF_OA  177792                      // 128*4
#define OFF_OD  178304                      // 128*4
#define OFF_OG  178816                      // 128*4
#define OFF_OS  179328                      // 128*4
#define SMEM_TOTAL 179840

__device__ __forceinline__ uint32_t smem_u32(const void* p) {
    uint32_t a;
    asm("{ .reg .u64 t; cvta.to.shared.u64 t, %1; cvt.u32.u64 %0, t; }" : "=r"(a) : "l"(p));
    return a;
}
__device__ __forceinline__ void cp16(uint32_t dst, const void* src) {
    asm volatile("cp.async.cg.shared.global [%0], [%1], 16;" :: "r"(dst), "l"(src) : "memory");
}
#define CP_COMMIT() asm volatile("cp.async.commit_group;" ::: "memory")
#define CP_WAIT1()  asm volatile("cp.async.wait_group 1;" ::: "memory")

// pack two f32 -> bf16x2: bits[31:16] = hi (k-odd), bits[15:0] = lo (k-even)
__device__ __forceinline__ uint32_t pack_bf16x2(float hi, float lo) {
    uint32_t d;
    asm("cvt.rn.bf16x2.f32 %0, %1, %2;" : "=r"(d) : "f"(hi), "f"(lo));
    return d;
}
__device__ __forceinline__ uint32_t hmul2(uint32_t a, uint32_t b) {
    uint32_t d;
    asm("mul.rn.bf16x2 %0, %1, %2;" : "=r"(d) : "r"(a), "r"(b));
    return d;
}

__device__ __forceinline__ void mma_bf16(float* d, const uint32_t* a, const uint32_t* b) {
    asm volatile(
        "mma.sync.aligned.m16n8k16.row.col.f32.bf16.bf16.f32 "
        "{%0,%1,%2,%3}, {%4,%5,%6,%7}, {%8,%9}, {%0,%1,%2,%3};"
        : "+f"(d[0]), "+f"(d[1]), "+f"(d[2]), "+f"(d[3])
        : "r"(a[0]), "r"(a[1]), "r"(a[2]), "r"(a[3]), "r"(b[0]), "r"(b[1]));
}

// ---------------- prep: fused packg + packwb + tables ----------------
__global__ void prep_kernel(const float* __restrict__ g_i,
                            const float* __restrict__ W1,
                            const float* __restrict__ b1,
                            const float* __restrict__ dist_embed,
                            const float* __restrict__ genre_embed,
                            const float* __restrict__ speaker_embed) {
    int idx = blockIdx.x * blockDim.x + threadIdx.x;
    if (idx < NPACKG) {
        float lo = g_i[2 * idx], hi = g_i[2 * idx + 1];
        g_gb[idx] = pack_bf16x2(hi, lo);
        return;
    }
    idx -= NPACKG;
    if (idx < NPACKW) {
        int c = idx / WCHUNK;
        int rem0 = idx % WCHUNK;
        int row = rem0 / WROW;
        int o = rem0 % WROW;
        uint32_t val = 0;
        if (o < 40) {
            int ng = row >> 5, lane = row & 31;
            int gidx = lane >> 2, tig = lane & 3;
            int s = o / 20, rem = o % 20;
            int j = rem >> 1, r = rem & 1;
            int n = 80 * ng + 8 * j + gidx;
            int kb = 32 * c + 16 * s + 2 * tig + 8 * r;
            float lo = (n < H_DIM) ? W1[(1024 + kb) * H_DIM + n] : 0.f;
            float hi = (n < H_DIM) ? W1[(1024 + kb + 1) * H_DIM + n] : 0.f;
            val = pack_bf16x2(hi, lo);
        }
        g_Wb[idx] = val;
        return;
    }
    idx -= NPACKW;
    if (idx < 10 * H_DIM) {
        int d = idx / H_DIM, j = idx % H_DIM;
        float acc = b1[j];
        #pragma unroll
        for (int t = 0; t < 20; t++)
            acc += dist_embed[d * 20 + t] * W1[(1536 + t) * H_DIM + j];
        g_Ed[d * ASTR + j] = acc;
    } else if (idx < 17 * H_DIM) {
        int r = idx - 10 * H_DIM;
        int d = r / H_DIM, j = r % H_DIM;
        float acc = 0.f;
        #pragma unroll
        for (int t = 0; t < 20; t++)
            acc += genre_embed[d * 20 + t] * W1[(1556 + t) * H_DIM + j];
        g_Eg[d * ASTR + j] = acc;
    } else if (idx < 20 * H_DIM) {
        int r = idx - 17 * H_DIM;
        int d = r / H_DIM, j = r % H_DIM;
        float acc = 0.f;
        #pragma unroll
        for (int t = 0; t < 20; t++)
            acc += speaker_embed[d * 20 + t] * W1[(1576 + t) * H_DIM + j];
        g_Es[d * ASTR + j] = acc;
    }
}

// ---------------- A/B precompute: 1024 blocks (A/B split, 8 rows each) ----------------
__global__ __launch_bounds__(160) void ab_kernel(const float* __restrict__ g_i,
                                                 const float* __restrict__ W1) {
    __shared__ float sg[ABR][G_DIM];
    const int blk  = blockIdx.x;
    const int half = blk & 1;              // 0 -> A, 1 -> B
    const int n0   = (blk >> 1) * ABR;
    for (int idx = threadIdx.x; idx < ABR * G_DIM; idx += blockDim.x) {
        int r = idx / G_DIM, k = idx % G_DIM;
        sg[r][k] = g_i[(n0 + r) * G_DIM + k];
    }
    __syncthreads();
    int j = threadIdx.x;
    if (j < H_DIM) {
        float acc[ABR];
        #pragma unroll
        for (int r = 0; r < ABR; r++) acc[r] = 0.f;
        const float* Wp = W1 + (size_t)half * G_DIM * H_DIM + j;
        #pragma unroll 4
        for (int k = 0; k < G_DIM; k++) {
            float wv = Wp[(size_t)k * H_DIM];
            #pragma unroll
            for (int r = 0; r < ABR; r++) acc[r] += sg[r][k] * wv;
        }
        float* dst = half ? g_B : g_A;
        #pragma unroll
        for (int r = 0; r < ABR; r++) dst[(n0 + r) * ASTR + j] = acc[r];
    }
}

// ---------------- main: 3-stage cp.async-pipelined bf16 m16n8k16 fused kernel ----------------
// CTA = 128 pairs = 2 spans, 512 threads = 16 warps (8 m-groups x 2 n-groups).
// Warp owns 1 m-tile (16 rows) x 10 n-tiles (8 cols). K = 16 chunks of 32 (2 k16-steps).
// 3 buffers, distance-2 prefetch issued BEFORE compute -> one barrier per chunk.
__global__ __launch_bounds__(512, 1) void main_kernel(
    const float* __restrict__ ms,
    const float* __restrict__ W2, const float* __restrict__ b2,
    const int* __restrict__ mention_ids, const int* __restrict__ antecedent_ids,
    const int* __restrict__ distances, const int* __restrict__ genres,
    const int* __restrict__ speakers, const int* __restrict__ ant_counts,
    float* __restrict__ out)
{
    extern __shared__ __align__(16) char smem[];
    const uint32_t sbase = smem_u32(smem);
    float*    sAdd = (float*)(smem + OFF_ADD);
    float*    sW2  = (float*)(smem + OFF_W2);
    float*    sMS  = (float*)(smem + OFF_MS);
    int*      sm_m = (int*)(smem + OFF_MID);
    int*      sm_a = (int*)(smem + OFF_AID);
    float*    sPt  = (float*)(smem + OFF_PT);
    float*    sSc  = (float*)(smem + OFF_SC);
    int*      sOM  = (int*)(smem + OFF_OM);
    int*      sOA  = (int*)(smem + OFF_OA);
    int*      sOD  = (int*)(smem + OFF_OD);
    int*      sOG  = (int*)(smem + OFF_OG);
    int*      sOS  = (int*)(smem + OFF_OS);

    const int t    = threadIdx.x;
    const int w    = t >> 5;
    const int lane = t & 31;
    const int gidx = lane >> 2;
    const int tig  = lane & 3;
    const int mg   = w >> 1;      // 0..7, 16 rows each
    const int ng   = w & 1;       // 0..1, 80 cols each
    const int pbase = blockIdx.x * 128;

    if (t < 128) {
        int gp = pbase + t;
        int m = mention_ids[gp], a = antecedent_ids[gp];
        sm_m[t] = m; sm_a[t] = a;
        int d = distances[gp];
        int bkt = (d >= 1) + (d >= 2) + (d >= 3) + (d >= 4) +
                  (d >= 8) + (d >= 16) + (d >= 32) + (d >= 64);
        sOM[t] = m * A4S;
        sOA[t] = a * A4S;
        sOD[t] = bkt * A4S;
        sOG[t] = genres[gp] * A4S;
        sOS[t] = speakers[gp] * A4S;
    }
    if (t < NPAD) sW2[t] = (t < H_DIM) ? W2[t] : 0.f;
    __syncthreads();

    // ---- per-thread cp.async slot pointers (fixed across chunks) ----
    const int p  = t >> 2;
    const int q  = t & 3;
    const uint32_t* srcM = g_gb + (size_t)sm_m[p] * (G_DIM / 2) + 4 * q;
    const uint32_t* srcA = g_gb + (size_t)sm_a[p] * (G_DIM / 2) + 4 * q;
    const uint32_t dMA = (uint32_t)(p * MAW + 4 * q) * 4u;
    const bool vW1 = (t + 512) < (WCHUNK / 4);

    // ---- prologue: prefetch chunks 0,1 into buffers 0,1 ----
    #pragma unroll
    for (int b = 0; b < 2; b++) {
        cp16(sbase + OFF_M0 + b * SZ_MA + dMA, srcM + b * 16);
        cp16(sbase + OFF_A0 + b * SZ_MA + dMA, srcA + b * 16);
        cp16(sbase + OFF_W0 + b * SZ_W + t * 16, g_Wb + b * WCHUNK + t * 4);
        if (vW1) cp16(sbase + OFF_W0 + b * SZ_W + (t + 512) * 16, g_Wb + b * WCHUNK + (t + 512) * 4);
        CP_COMMIT();
    }

    // ---- upfront Add-gather: float4 over padded-stride tables ----
    {
        const float4* A4 = (const float4*)g_A;
        const float4* B4 = (const float4*)g_B;
        const float4* D4 = (const float4*)g_Ed;
        const float4* G4 = (const float4*)g_Eg;
        const float4* S4 = (const float4*)g_Es;
        #pragma unroll
        for (int it = 0; it < 10; it++) {
            int grp = t + 512 * it;
            if (grp < 128 * A4S) {
                int pr = grp / A4S, jq = grp % A4S;
                float4 va = A4[sOM[pr] + jq];
                float4 vb = B4[sOA[pr] + jq];
                float4 vd = D4[sOD[pr] + jq];
                float4 vg = G4[sOG[pr] + jq];
                float4 vs = S4[sOS[pr] + jq];
                int j = 4 * jq;
                float r0 = va.x + vb.x + vd.x + vg.x + vs.x;
                float r1 = va.y + vb.y + vd.y + vg.y + vs.y;
                float r2 = va.z + vb.z + vd.z + vg.z + vs.z;
                float r3 = va.w + vb.w + vd.w + vg.w + vs.w;
                float* dst = sAdd + pr * ADDP + j;
                if (j     < H_DIM) dst[0] = r0;
                if (j + 1 < H_DIM) dst[1] = r1;
                if (j + 2 < ADDP) dst[2] = (j + 2 < H_DIM) ? r2 : 0.f;
                if (j + 3 < ADDP) dst[3] = (j + 3 < H_DIM) ? r3 : 0.f;
            }
        }
    }
    if (t < 128)
        sMS[t] = ms[sm_m[t]] + ms[sm_a[t]] + b2[0];

    float acc[10][4];
    #pragma unroll
    for (int j = 0; j < 10; j++)
        #pragma unroll
        for (int e = 0; e < 4; e++) acc[j][e] = 0.f;

    const uint32_t wrow = (uint32_t)((ng * 32 + lane) * WROW);
    const int abase0 = (16 * mg + gidx) * MAW + tig;

    for (int c = 0; c < 16; c++) {
        const int b = c % 3;

        CP_WAIT1();          // chunk c arrived (chunk c+1 may still be in flight)
        __syncthreads();     // CTA-wide visibility + all warps past iteration c-1

        // ---- prefetch chunk c+2 into buffer (c+2)%3 (consumed in iter c-1) ----
        if (c + 2 < 16) {
            const int cc = c + 2, bb = (c + 2) % 3;
            cp16(sbase + OFF_M0 + bb * SZ_MA + dMA, srcM + cc * 16);
            cp16(sbase + OFF_A0 + bb * SZ_MA + dMA, srcA + cc * 16);
            cp16(sbase + OFF_W0 + bb * SZ_W + t * 16, g_Wb + cc * WCHUNK + t * 4);
            if (vW1) cp16(sbase + OFF_W0 + bb * SZ_W + (t + 512) * 16, g_Wb + cc * WCHUNK + (t + 512) * 4);
        }
        CP_COMMIT();

        // ---- compute: 2 k16-steps of m16n8k16 ----
        const uint32_t* pM = (const uint32_t*)(smem + OFF_M0 + b * SZ_MA);
        const uint32_t* pA = (const uint32_t*)(smem + OFF_A0 + b * SZ_MA);
        const uint32_t* pW = (const uint32_t*)(smem + OFF_W0 + b * SZ_W);
        #pragma unroll
        for (int s = 0; s < 2; s++) {
            const int base = abase0 + 8 * s;
            uint32_t afr[4];
            afr[0] = hmul2(pM[base],               pA[base]);
            afr[1] = hmul2(pM[base + 8 * MAW],     pA[base + 8 * MAW]);
            afr[2] = hmul2(pM[base + 4],           pA[base + 4]);
            afr[3] = hmul2(pM[base + 8 * MAW + 4], pA[base + 8 * MAW + 4]);
            uint32_t wb[20];
            #pragma unroll
            for (int i = 0; i < 5; i++) {
                uint4 qd = *(const uint4*)(pW + wrow + 20 * s + 4 * i);
                wb[4 * i + 0] = qd.x; wb[4 * i + 1] = qd.y;
                wb[4 * i + 2] = qd.z; wb[4 * i + 3] = qd.w;
            }
            #pragma unroll
            for (int j = 0; j < 10; j++) {
                uint32_t bfr[2] = { wb[2 * j], wb[2 * j + 1] };
                mma_bf16(acc[j], afr, bfr);
            }
        }
    }
    __syncthreads();

    // ---- epilogue: + Add, ReLU, dot W2 ----
    {
        float rp0 = 0.f, rp1 = 0.f;
        const int rowA = 16 * mg + gidx;
        const int rowB = rowA + 8;
        #pragma unroll
        for (int j = 0; j < 10; j++) {
            int col0 = 8 * (10 * ng + j) + 2 * tig;
            float w0 = sW2[col0], w1 = sW2[col0 + 1];
            float h;
            h = acc[j][0] + ((col0     < ADDP) ? sAdd[rowA * ADDP + col0]     : 0.f);
            rp0 += fmaxf(h, 0.f) * w0;
            h = acc[j][1] + ((col0 + 1 < ADDP) ? sAdd[rowA * ADDP + col0 + 1] : 0.f);
            rp0 += fmaxf(h, 0.f) * w1;
            h = acc[j][2] + ((col0     < ADDP) ? sAdd[rowB * ADDP + col0]     : 0.f);
            rp1 += fmaxf(h, 0.f) * w0;
            h = acc[j][3] + ((col0 + 1 < ADDP) ? sAdd[rowB * ADDP + col0 + 1] : 0.f);
            rp1 += fmaxf(h, 0.f) * w1;
        }
        #pragma unroll
        for (int off = 1; off <= 2; off <<= 1) {
            rp0 += __shfl_xor_sync(0xffffffffu, rp0, off);
            rp1 += __shfl_xor_sync(0xffffffffu, rp1, off);
        }
        if (tig == 0) {
            sPt[rowA * 2 + ng] = rp0;
            sPt[rowB * 2 + ng] = rp1;
        }
    }
    __syncthreads();
    if (t < 128)
        sSc[t] = sPt[t * 2 + 0] + sPt[t * 2 + 1] + sMS[t];
    __syncthreads();

    // ---- fused per-span softmax (2 spans per CTA) ----
    if (w < 2) {
        int s = blockIdx.x * 2 + w;
        int cnt = ant_counts[s];
        float v0 = sSc[w * 64 + lane], v1 = sSc[w * 64 + lane + 32];
        bool val0 = lane < cnt, val1 = (lane + 32) < cnt;
        float mx = 0.f;  // epsilon logit = 0
        if (val0) mx = fmaxf(mx, v0);
        if (val1) mx = fmaxf(mx, v1);
        #pragma unroll
        for (int off = 16; off >= 1; off >>= 1)
            mx = fmaxf(mx, __shfl_xor_sync(0xffffffffu, mx, off));
        float e0 = val0 ? expf(v0 - mx) : 0.f;
        float e1 = val1 ? expf(v1 - mx) : 0.f;
        float sum = e0 + e1;
        #pragma unroll
        for (int off = 16; off >= 1; off >>= 1)
            sum += __shfl_xor_sync(0xffffffffu, sum, off);
        float eps = expf(-mx);
        sum += eps;
        float inv = 1.0f / sum;
        float* orow = out + (size_t)s * (K_ANT + 1);
        orow[lane]      = val0 ? e0 * inv : 1000.0f;
        orow[lane + 32] = val1 ? e1 * inv : 1000.0f;
        if (lane == 0) orow[K_ANT] = eps * inv;
    }
}

extern "C" void kernel_launch(void* const* d_in, const int* in_sizes, int n_in,
                              void* d_out, int out_size) {
    const float* g_i            = (const float*)d_in[0];
    const float* mention_scores = (const float*)d_in[1];
    const float* dist_embed     = (const float*)d_in[2];
    const float* genre_embed    = (const float*)d_in[3];
    const float* speaker_embed  = (const float*)d_in[4];
    const float* W1             = (const float*)d_in[5];
    const float* b1             = (const float*)d_in[6];
    const float* W2             = (const float*)d_in[7];
    const float* b2             = (const float*)d_in[8];
    const int*   mention_ids    = (const int*)d_in[9];
    const int*   antecedent_ids = (const int*)d_in[10];
    const int*   distances      = (const int*)d_in[11];
    const int*   genres         = (const int*)d_in[12];
    const int*   speakers       = (const int*)d_in[13];
    const int*   ant_counts     = (const int*)d_in[14];
    float* out = (float*)d_out;

    cudaFuncSetAttribute(main_kernel, cudaFuncAttributeMaxDynamicSharedMemorySize, SMEM_TOTAL);

    prep_kernel<<<(NPREP + 255) / 256, 256>>>(g_i, W1, b1, dist_embed,
                                              genre_embed, speaker_embed);
    ab_kernel<<<(N_MENT / ABR) * 2, 160>>>(g_i, W1);
    main_kernel<<<S_SPANS / 2, 512, SMEM_TOTAL>>>(mention_scores, W2, b2,
                                                  mention_ids, antecedent_ids, distances,
                                                  genres, speakers, ant_counts, out);
}